// round 1
// baseline (speedup 1.0000x reference)
#include <cuda_runtime.h>
#include <math.h>

// Problem constants
#define BB 8
#define SS 2048
#define DD 128
#define TT 16384          // BB*SS tokens
#define WW 64             // window
#define NHH 8
#define HDD 16

// Scratch layout (floats)
#define OFF_QKV 0u                 // 16384*384
#define OFF_A   6291456u           // 16384*128
#define OFF_B   8388608u           // 16384*128
#define OFF_H   10485760u          // 16384*512
#define OFF_C   18874368u          // 16384*128
#define OFF_SE  20971520u
#define OFF_TE  23068672u
#define OFF_SN  25165824u
#define OFF_TN  27262976u
#define OFF_M   29360128u          // 8*128*128
#define OFF_SIM 29491200u          // 16384
#define SCR_TOT 29507584u

__device__ float g_scr[SCR_TOT];

enum { EP_BIAS = 0, EP_RES = 1, EP_GELU = 2, EP_FINAL = 3 };

// C[M,N] = A[M,K] @ W[N,K]^T + bias, epilogue variants.
// Grid: (N/64, M/64), block 256 threads. ldc is row stride of C (and R).
__global__ __launch_bounds__(256) void gemm_k(
    const float* __restrict__ A, const float* __restrict__ Wt,
    const float* __restrict__ bias, float* __restrict__ C,
    const float* __restrict__ R, const float* __restrict__ rs,
    int K, int ldc, int mode)
{
    __shared__ float As[16][65];
    __shared__ float Ws[16][65];
    const int bm = blockIdx.y * 64;
    const int bn = blockIdx.x * 64;
    const int tid = threadIdx.x;
    const int tx = tid & 15, ty = tid >> 4;
    float acc[4][4] = {};
    for (int k0 = 0; k0 < K; k0 += 16) {
        #pragma unroll
        for (int l = 0; l < 4; l++) {
            int idx = tid + l * 256;
            int r = idx >> 4, c = idx & 15;
            As[c][r] = A[(size_t)(bm + r) * K + k0 + c];
            Ws[c][r] = Wt[(size_t)(bn + r) * K + k0 + c];
        }
        __syncthreads();
        #pragma unroll
        for (int kk = 0; kk < 16; kk++) {
            float a[4], b[4];
            #pragma unroll
            for (int i = 0; i < 4; i++) a[i] = As[kk][ty * 4 + i];
            #pragma unroll
            for (int j = 0; j < 4; j++) b[j] = Ws[kk][tx * 4 + j];
            #pragma unroll
            for (int i = 0; i < 4; i++)
                #pragma unroll
                for (int j = 0; j < 4; j++)
                    acc[i][j] += a[i] * b[j];
        }
        __syncthreads();
    }
    #pragma unroll
    for (int i = 0; i < 4; i++) {
        int row = bm + ty * 4 + i;
        #pragma unroll
        for (int j = 0; j < 4; j++) {
            int col = bn + tx * 4 + j;
            float v = acc[i][j] + bias[col];
            if (mode == EP_RES) {
                v += R[(size_t)row * ldc + col];
            } else if (mode == EP_GELU) {
                v = 0.5f * v * (1.0f + erff(v * 0.70710678118654752f));
            } else if (mode == EP_FINAL) {
                v = R[(size_t)row * ldc + col] + rs[row] * v;
            }
            C[(size_t)row * ldc + col] = v;
        }
    }
}

// Local windowed causal attention. qkv: [t, 384] (q|k|v). out: [t, 128].
// Grid (256 windows, 8 heads), 64 threads (one per query row).
__global__ __launch_bounds__(64) void lw_attn_k(const float* __restrict__ qkv,
                                                float* __restrict__ out)
{
    int g = blockIdx.x;
    int h = blockIdx.y;
    int i = threadIdx.x;
    __shared__ float ks[64][17];
    __shared__ float vs[64][17];
    size_t tbase = (size_t)g * 64;
    const float* kp = qkv + (tbase + i) * 384 + 128 + h * 16;
    const float* vp = kp + 128;
    #pragma unroll
    for (int d = 0; d < 16; d++) { ks[i][d] = kp[d]; vs[i][d] = vp[d]; }
    float q[16];
    const float* qp = qkv + (tbase + i) * 384 + h * 16;
    #pragma unroll
    for (int d = 0; d < 16; d++) q[d] = qp[d];
    __syncthreads();
    float sc[64];
    float mx = -1e30f;
    #pragma unroll
    for (int j = 0; j < 64; j++) {
        float dv = 0.f;
        #pragma unroll
        for (int d = 0; d < 16; d++) dv += q[d] * ks[j][d];
        sc[j] = (j <= i) ? dv * 0.25f : -INFINITY;
        mx = fmaxf(mx, sc[j]);
    }
    float sum = 0.f;
    #pragma unroll
    for (int j = 0; j < 64; j++) { float e = expf(sc[j] - mx); sc[j] = e; sum += e; }
    float o[16] = {};
    #pragma unroll
    for (int j = 0; j < 64; j++) {
        float w = sc[j];
        #pragma unroll
        for (int d = 0; d < 16; d++) o[d] += w * vs[j][d];
    }
    float inv = 1.f / sum;
    float* op = out + (tbase + i) * 128 + h * 16;
    #pragma unroll
    for (int d = 0; d < 16; d++) op[d] = o[d] * inv;
}

// Interaction MHA: len=B(=8) attention at each sequence position s.
// qkv layout [t=b*S+s, 384]. Grid: S blocks, 64 threads = (head, query-b).
__global__ __launch_bounds__(64) void int_attn_k(const float* __restrict__ qkv,
                                                 float* __restrict__ out)
{
    int s = blockIdx.x;
    int tid = threadIdx.x;
    __shared__ float kvs[8][256];  // [jb][k(0:128)|v(128:256)]
    for (int idx = tid; idx < 8 * 256; idx += 64) {
        int jb = idx >> 8, c = idx & 255;
        kvs[jb][c] = qkv[((size_t)jb * SS + s) * 384 + 128 + c];
    }
    __syncthreads();
    int h = tid >> 3, qb = tid & 7;
    float q[16];
    const float* qp = qkv + ((size_t)qb * SS + s) * 384 + h * 16;
    #pragma unroll
    for (int d = 0; d < 16; d++) q[d] = qp[d];
    float sc[8];
    float mx = -1e30f;
    #pragma unroll
    for (int jb = 0; jb < 8; jb++) {
        float dv = 0.f;
        #pragma unroll
        for (int d = 0; d < 16; d++) dv += q[d] * kvs[jb][h * 16 + d];
        sc[jb] = dv * 0.25f;
        mx = fmaxf(mx, sc[jb]);
    }
    float sum = 0.f;
    #pragma unroll
    for (int jb = 0; jb < 8; jb++) { float e = expf(sc[jb] - mx); sc[jb] = e; sum += e; }
    float o[16] = {};
    #pragma unroll
    for (int jb = 0; jb < 8; jb++) {
        float w = sc[jb];
        #pragma unroll
        for (int d = 0; d < 16; d++) o[d] += w * kvs[jb][128 + h * 16 + d];
    }
    float inv = 1.f / sum;
    float* op = out + ((size_t)qb * SS + s) * 128 + h * 16;
    #pragma unroll
    for (int d = 0; d < 16; d++) op[d] = o[d] * inv;
}

// In-place LayerNorm over last dim (128). Grid T, block 128.
__global__ __launch_bounds__(128) void ln_k(float* __restrict__ x,
                                            const float* __restrict__ g,
                                            const float* __restrict__ b)
{
    int t = blockIdx.x, d = threadIdx.x;
    float v = x[(size_t)t * 128 + d];
    float s = v, s2 = v * v;
    #pragma unroll
    for (int o = 16; o; o >>= 1) {
        s += __shfl_xor_sync(0xffffffffu, s, o);
        s2 += __shfl_xor_sync(0xffffffffu, s2, o);
    }
    __shared__ float ss[4], ss2[4];
    int w = d >> 5;
    if ((d & 31) == 0) { ss[w] = s; ss2[w] = s2; }
    __syncthreads();
    s = ss[0] + ss[1] + ss[2] + ss[3];
    s2 = ss2[0] + ss2[1] + ss2[2] + ss2[3];
    float mu = s * (1.f / 128.f);
    float var = s2 * (1.f / 128.f) - mu * mu;
    x[(size_t)t * 128 + d] = (v - mu) * rsqrtf(var + 1e-5f) * g[d] + b[d];
}

// Cosine normalize rows of 128: o = e / max(||e||, 1e-8)
__global__ __launch_bounds__(128) void cosnorm_k(const float* __restrict__ e,
                                                 float* __restrict__ o)
{
    int t = blockIdx.x, d = threadIdx.x;
    float v = e[(size_t)t * 128 + d];
    float s2 = v * v;
    #pragma unroll
    for (int off = 16; off; off >>= 1) s2 += __shfl_xor_sync(0xffffffffu, s2, off);
    __shared__ float ss2[4];
    int w = d >> 5;
    if ((d & 31) == 0) ss2[w] = s2;
    __syncthreads();
    s2 = ss2[0] + ss2[1] + ss2[2] + ss2[3];
    float n = sqrtf(s2);
    float denom = fmaxf(n, 1e-8f);
    o[(size_t)t * 128 + d] = v / denom;
}

__global__ void zero_k(float* p, int n)
{
    int i = blockIdx.x * 256 + threadIdx.x;
    if (i < n) p[i] = 0.f;
}

// M[b][d][e] = sum_s sn[b,s,d]*tn[b,s,e]. Grid (16 splits, 8 batches), 256 thr.
__global__ __launch_bounds__(256) void m_k(const float* __restrict__ sn,
                                           const float* __restrict__ tn,
                                           float* __restrict__ M)
{
    int b = blockIdx.y;
    int s0 = blockIdx.x * 128;
    int tid = threadIdx.x;
    int tx = tid & 15, ty = tid >> 4;
    __shared__ float sns[16][129], tns[16][129];
    float acc[8][8] = {};
    const float* snb = sn + ((size_t)b * SS + s0) * 128;
    const float* tnb = tn + ((size_t)b * SS + s0) * 128;
    for (int s1 = 0; s1 < 128; s1 += 16) {
        for (int idx = tid; idx < 2048; idx += 256) {
            int r = idx >> 7, c = idx & 127;
            sns[r][c] = snb[(size_t)(s1 + r) * 128 + c];
            tns[r][c] = tnb[(size_t)(s1 + r) * 128 + c];
        }
        __syncthreads();
        #pragma unroll
        for (int ssx = 0; ssx < 16; ssx++) {
            float a[8], c8[8];
            #pragma unroll
            for (int i = 0; i < 8; i++) a[i] = sns[ssx][ty * 8 + i];
            #pragma unroll
            for (int j = 0; j < 8; j++) c8[j] = tns[ssx][tx * 8 + j];
            #pragma unroll
            for (int i = 0; i < 8; i++)
                #pragma unroll
                for (int j = 0; j < 8; j++)
                    acc[i][j] += a[i] * c8[j];
        }
        __syncthreads();
    }
    float* Mb = M + (size_t)b * 16384;
    #pragma unroll
    for (int i = 0; i < 8; i++)
        #pragma unroll
        for (int j = 0; j < 8; j++)
            atomicAdd(&Mb[(size_t)(ty * 8 + i) * 128 + tx * 8 + j], acc[i][j]);
}

// sim[b,i] = (1/S) * sn_i^T M_b tn_i. Grid (16 token tiles, 8 batches), 256 thr.
__global__ __launch_bounds__(256) void sim_k(const float* __restrict__ sn,
                                             const float* __restrict__ tn,
                                             const float* __restrict__ M,
                                             float* __restrict__ sim)
{
    int b = blockIdx.y;
    int s0 = blockIdx.x * 128;
    int tid = threadIdx.x;
    int tx = tid & 15, ty = tid >> 4;
    __shared__ float tnS[16][129];
    __shared__ float MS[16][129];
    __shared__ float simS[128];
    if (tid < 128) simS[tid] = 0.f;
    float acc[8][8] = {};
    const float* tnb = tn + ((size_t)b * SS + s0) * 128;
    const float* Mb = M + (size_t)b * 16384;
    for (int e0 = 0; e0 < 128; e0 += 16) {
        for (int idx = tid; idx < 2048; idx += 256) {
            int i = idx >> 4, ee = idx & 15;
            tnS[ee][i] = tnb[(size_t)i * 128 + e0 + ee];  // tn[token i, e]
            MS[ee][i] = Mb[(size_t)i * 128 + e0 + ee];    // M[d=i, e]
        }
        __syncthreads();
        #pragma unroll
        for (int ee = 0; ee < 16; ee++) {
            float a[8], c8[8];
            #pragma unroll
            for (int i = 0; i < 8; i++) a[i] = tnS[ee][ty * 8 + i];
            #pragma unroll
            for (int j = 0; j < 8; j++) c8[j] = MS[ee][tx * 8 + j];
            #pragma unroll
            for (int i = 0; i < 8; i++)
                #pragma unroll
                for (int j = 0; j < 8; j++)
                    acc[i][j] += a[i] * c8[j];  // U[i, d] += tn[i,e]*M[d,e]
        }
        __syncthreads();
    }
    const float* snb = sn + ((size_t)b * SS + s0) * 128;
    #pragma unroll
    for (int i = 0; i < 8; i++) {
        int tok = ty * 8 + i;
        float p = 0.f;
        #pragma unroll
        for (int j = 0; j < 8; j++)
            p += acc[i][j] * snb[(size_t)tok * 128 + tx * 8 + j];
        atomicAdd(&simS[tok], p);
    }
    __syncthreads();
    if (tid < 128)
        sim[(size_t)b * SS + s0 + tid] = simS[tid] * (1.f / 2048.f);
}

extern "C" void kernel_launch(void* const* d_in, const int* in_sizes, int n_in,
                              void* d_out, int out_size)
{
    const float* x        = (const float*)d_in[0];
    const float* sp       = (const float*)d_in[1];
    const float* tp       = (const float*)d_in[2];
    const float* lw_in_w  = (const float*)d_in[3];
    const float* lw_in_b  = (const float*)d_in[4];
    const float* lw_out_w = (const float*)d_in[5];
    const float* lw_out_b = (const float*)d_in[6];
    const float* spat_w   = (const float*)d_in[7];
    const float* spat_b   = (const float*)d_in[8];
    const float* temp_w   = (const float*)d_in[9];
    const float* temp_b   = (const float*)d_in[10];
    const float* int_in_w = (const float*)d_in[11];
    const float* int_in_b = (const float*)d_in[12];
    const float* int_out_w= (const float*)d_in[13];
    const float* int_out_b= (const float*)d_in[14];
    const float* ffn_w1   = (const float*)d_in[15];
    const float* ffn_b1   = (const float*)d_in[16];
    const float* ffn_w2   = (const float*)d_in[17];
    const float* ffn_b2   = (const float*)d_in[18];
    const float* ln1_g    = (const float*)d_in[19];
    const float* ln1_b    = (const float*)d_in[20];
    const float* ln2_g    = (const float*)d_in[21];
    const float* ln2_b    = (const float*)d_in[22];
    float* out = (float*)d_out;

    float* scr = nullptr;
    cudaGetSymbolAddress((void**)&scr, g_scr);
    float* qkv  = scr + OFF_QKV;
    float* bufa = scr + OFF_A;
    float* bufb = scr + OFF_B;
    float* bufh = scr + OFF_H;
    float* bufc = scr + OFF_C;
    float* bse  = scr + OFF_SE;
    float* bte  = scr + OFF_TE;
    float* bsn  = scr + OFF_SN;
    float* btn  = scr + OFF_TN;
    float* bM   = scr + OFF_M;
    float* bsim = scr + OFF_SIM;

    // --- local window attention path ---
    gemm_k<<<dim3(6, 256), 256>>>(x, lw_in_w, lw_in_b, qkv, nullptr, nullptr, 128, 384, EP_BIAS);
    lw_attn_k<<<dim3(256, 8), 64>>>(qkv, bufa);
    gemm_k<<<dim3(2, 256), 256>>>(bufa, lw_out_w, lw_out_b, bufb, x, nullptr, 128, 128, EP_RES);
    ln_k<<<TT, 128>>>(bufb, ln1_g, ln1_b);
    // --- FFN ---
    gemm_k<<<dim3(8, 256), 256>>>(bufb, ffn_w1, ffn_b1, bufh, nullptr, nullptr, 128, 512, EP_GELU);
    gemm_k<<<dim3(2, 256), 256>>>(bufh, ffn_w2, ffn_b2, bufc, bufb, nullptr, 512, 128, EP_RES);
    ln_k<<<TT, 128>>>(bufc, ln2_g, ln2_b);
    // --- spatio-temporal embeddings ---
    gemm_k<<<dim3(2, 256), 256>>>(sp, spat_w, spat_b, bse, nullptr, nullptr, 128, 128, EP_BIAS);
    gemm_k<<<dim3(2, 256), 256>>>(tp, temp_w, temp_b, bte, nullptr, nullptr, 128, 128, EP_BIAS);
    cosnorm_k<<<TT, 128>>>(bse, bsn);
    cosnorm_k<<<TT, 128>>>(bte, btn);
    // --- sim via M factorization ---
    zero_k<<<512, 256>>>(bM, 8 * 128 * 128);
    m_k<<<dim3(16, 8), 256>>>(bsn, btn, bM);
    sim_k<<<dim3(16, 8), 256>>>(bsn, btn, bM, bsim);
    // --- interaction MHA (len = B = 8) ---
    gemm_k<<<dim3(2, 256), 256>>>(bse, int_in_w, int_in_b, qkv, nullptr, nullptr, 128, 384, EP_BIAS);
    gemm_k<<<dim3(4, 256), 256>>>(bte, int_in_w + 128 * 128, int_in_b + 128, qkv + 128,
                                  nullptr, nullptr, 128, 384, EP_BIAS);
    int_attn_k<<<SS, 64>>>(qkv, bufa);
    // --- final: out = x2 + sim[t] * (attn @ Wout^T + bout) ---
    gemm_k<<<dim3(2, 256), 256>>>(bufa, int_out_w, int_out_b, out, bufc, bsim, 128, 128, EP_FINAL);
}

// round 3
// speedup vs baseline: 1.4815x; 1.4815x over previous
#include <cuda_runtime.h>
#include <cuda_bf16.h>
#include <cstdint>
#include <math.h>

// Problem constants
#define BB 8
#define SS 2048
#define TT 16384

// Scratch layout (floats)
#define OFF_QKV 0u
#define OFF_A   6291456u
#define OFF_B   8388608u
#define OFF_H   10485760u
#define OFF_C   18874368u
#define OFF_SE  20971520u
#define OFF_TE  23068672u
#define OFF_SN  25165824u
#define OFF_TN  27262976u
#define OFF_M   29360128u
#define OFF_SIM 29491200u
#define SCR_TOT 29507584u

__device__ float g_scr[SCR_TOT];

enum { EP_BIAS = 0, EP_RES = 1, EP_GELU = 2, EP_FINAL = 3, EP_SIMDOT = 4 };

__device__ __forceinline__ uint32_t smem_to_u32(const void* p) {
    uint32_t a;
    asm("{ .reg .u64 t; cvta.to.shared.u64 t, %1; cvt.u32.u64 %0, t; }" : "=r"(a) : "l"(p));
    return a;
}

#define LDSM4(r0, r1, r2, r3, addr) \
    asm volatile("ldmatrix.sync.aligned.m8n8.x4.shared.b16 {%0,%1,%2,%3}, [%4];" \
        : "=r"(r0), "=r"(r1), "=r"(r2), "=r"(r3) : "r"(addr))
#define LDSM4T(r0, r1, r2, r3, addr) \
    asm volatile("ldmatrix.sync.aligned.m8n8.x4.trans.shared.b16 {%0,%1,%2,%3}, [%4];" \
        : "=r"(r0), "=r"(r1), "=r"(r2), "=r"(r3) : "r"(addr))
#define LDSM2(r0, r1, addr) \
    asm volatile("ldmatrix.sync.aligned.m8n8.x2.shared.b16 {%0,%1}, [%2];" \
        : "=r"(r0), "=r"(r1) : "r"(addr))
#define LDSM2T(r0, r1, addr) \
    asm volatile("ldmatrix.sync.aligned.m8n8.x2.trans.shared.b16 {%0,%1}, [%2];" \
        : "=r"(r0), "=r"(r1) : "r"(addr))

#define MMA_BF16(c, a, b) \
    asm volatile("mma.sync.aligned.m16n8k16.row.col.f32.bf16.bf16.f32 " \
        "{%0,%1,%2,%3}, {%4,%5,%6,%7}, {%8,%9}, {%0,%1,%2,%3};" \
        : "+f"((c)[0]), "+f"((c)[1]), "+f"((c)[2]), "+f"((c)[3]) \
        : "r"((a)[0]), "r"((a)[1]), "r"((a)[2]), "r"((a)[3]), "r"((b)[0]), "r"((b)[1]))

__device__ __forceinline__ void cvt_split4(float4 v, uint2& hv, uint2& lv) {
    __nv_bfloat16 h0 = __float2bfloat16_rn(v.x);
    __nv_bfloat16 h1 = __float2bfloat16_rn(v.y);
    __nv_bfloat16 h2 = __float2bfloat16_rn(v.z);
    __nv_bfloat16 h3 = __float2bfloat16_rn(v.w);
    __nv_bfloat16 l0 = __float2bfloat16_rn(v.x - __bfloat162float(h0));
    __nv_bfloat16 l1 = __float2bfloat16_rn(v.y - __bfloat162float(h1));
    __nv_bfloat16 l2 = __float2bfloat16_rn(v.z - __bfloat162float(h2));
    __nv_bfloat16 l3 = __float2bfloat16_rn(v.w - __bfloat162float(h3));
    hv.x = (uint32_t)__bfloat16_as_ushort(h0) | ((uint32_t)__bfloat16_as_ushort(h1) << 16);
    hv.y = (uint32_t)__bfloat16_as_ushort(h2) | ((uint32_t)__bfloat16_as_ushort(h3) << 16);
    lv.x = (uint32_t)__bfloat16_as_ushort(l0) | ((uint32_t)__bfloat16_as_ushort(l1) << 16);
    lv.y = (uint32_t)__bfloat16_as_ushort(l2) | ((uint32_t)__bfloat16_as_ushort(l3) << 16);
}

__device__ __forceinline__ float gelu_f(float v) {
    return 0.5f * v * (1.0f + erff(v * 0.70710678118654752f));
}

// smem byte offsets for gemm_mma: 128 rows x 40 bf16 (80B stride) per buffer
#define GSA_H 0
#define GSA_L 10240
#define GSW_H 20480
#define GSW_L 30720
#define GSM_TOT 40960

// ================= generic mma.sync GEMM: C[M,N] = A[M,K] @ W[N,K]^T =================
// grid (N/128, M/128), 256 threads (8 warps, 2x4). bf16 2-way split, fp32 acc.
__global__ void __launch_bounds__(256) gemm_mma(
    const float* __restrict__ A, const float* __restrict__ W,
    const float* __restrict__ bias, float* __restrict__ C,
    const float* __restrict__ R, const float* __restrict__ rs,
    int K, int ldc, int mode, int batchW)
{
    extern __shared__ char smem[];
    uint32_t sb = smem_to_u32(smem);
    const int tid = threadIdx.x, lane = tid & 31, wid = tid >> 5;
    const int wm = wid >> 2, wn = wid & 3;
    const int lr = lane >> 2, lc = lane & 3;
    const int bm = blockIdx.y * 128, bn = blockIdx.x * 128;
    if (batchW) W += (size_t)(bm >> 11) * (size_t)batchW;

    const int r = tid >> 1, half = tid & 1;
    const float* Arow = A + (size_t)(bm + r) * K + half * 16;
    const float* Wrow = W + (size_t)(bn + r) * K + half * 16;
    char* stA = smem + r * 80 + half * 32;
    char* stW = smem + GSW_H + r * 80 + half * 32;

    float acc[4][4][4];
    #pragma unroll
    for (int i = 0; i < 4; i++)
        #pragma unroll
        for (int j = 0; j < 4; j++)
            #pragma unroll
            for (int k = 0; k < 4; k++) acc[i][j][k] = 0.f;

    float4 pa[4], pw[4];
    #pragma unroll
    for (int i = 0; i < 4; i++) {
        pa[i] = *(const float4*)(Arow + i * 4);
        pw[i] = *(const float4*)(Wrow + i * 4);
    }

    const int nch = K >> 5;
    for (int c = 0; c < nch; c++) {
        #pragma unroll
        for (int i = 0; i < 4; i++) {
            uint2 hv, lv;
            cvt_split4(pa[i], hv, lv);
            *(uint2*)(stA + i * 8) = hv;
            *(uint2*)(stA + GSA_L + i * 8) = lv;
            cvt_split4(pw[i], hv, lv);
            *(uint2*)(stW + i * 8) = hv;
            *(uint2*)(stW + GSA_L + i * 8) = lv;
        }
        __syncthreads();
        if (c + 1 < nch) {
            #pragma unroll
            for (int i = 0; i < 4; i++) {
                pa[i] = *(const float4*)(Arow + (c + 1) * 32 + i * 4);
                pw[i] = *(const float4*)(Wrow + (c + 1) * 32 + i * 4);
            }
        }
        #pragma unroll
        for (int ks = 0; ks < 2; ks++) {
            uint32_t ah[4][4], al[4][4], bh[4][2], bl[4][2];
            #pragma unroll
            for (int mt = 0; mt < 4; mt++) {
                uint32_t addr = sb + GSA_H + (uint32_t)((wm * 64 + mt * 16 + (lane & 15)) * 80
                               + ks * 32 + ((lane >> 4) & 1) * 16);
                LDSM4(ah[mt][0], ah[mt][1], ah[mt][2], ah[mt][3], addr);
                LDSM4(al[mt][0], al[mt][1], al[mt][2], al[mt][3], addr + GSA_L);
            }
            #pragma unroll
            for (int nt = 0; nt < 4; nt++) {
                uint32_t addr = sb + GSW_H + (uint32_t)((wn * 32 + nt * 8 + (lane & 7)) * 80
                               + ks * 32 + ((lane >> 3) & 1) * 16);
                LDSM2(bh[nt][0], bh[nt][1], addr);
                LDSM2(bl[nt][0], bl[nt][1], addr + GSA_L);
            }
            #pragma unroll
            for (int mt = 0; mt < 4; mt++)
                #pragma unroll
                for (int nt = 0; nt < 4; nt++) {
                    MMA_BF16(acc[mt][nt], ah[mt], bh[nt]);
                    MMA_BF16(acc[mt][nt], ah[mt], bl[nt]);
                    MMA_BF16(acc[mt][nt], al[mt], bh[nt]);
                }
        }
        __syncthreads();
    }

    if (mode == EP_SIMDOT) {
        float* simS = (float*)smem;
        if (tid < 128) simS[tid] = 0.f;
        __syncthreads();
        #pragma unroll
        for (int mt = 0; mt < 4; mt++) {
            int row0 = bm + wm * 64 + mt * 16 + lr;
            float d0 = 0.f, d1 = 0.f;
            #pragma unroll
            for (int nt = 0; nt < 4; nt++) {
                int col = bn + wn * 32 + nt * 8 + 2 * lc;
                float2 s0 = *(const float2*)(R + (size_t)row0 * 128 + col);
                float2 s1 = *(const float2*)(R + (size_t)(row0 + 8) * 128 + col);
                d0 += acc[mt][nt][0] * s0.x + acc[mt][nt][1] * s0.y;
                d1 += acc[mt][nt][2] * s1.x + acc[mt][nt][3] * s1.y;
            }
            d0 += __shfl_xor_sync(0xffffffffu, d0, 1);
            d0 += __shfl_xor_sync(0xffffffffu, d0, 2);
            d1 += __shfl_xor_sync(0xffffffffu, d1, 1);
            d1 += __shfl_xor_sync(0xffffffffu, d1, 2);
            if (lc == 0) {
                atomicAdd(&simS[wm * 64 + mt * 16 + lr], d0);
                atomicAdd(&simS[wm * 64 + mt * 16 + lr + 8], d1);
            }
        }
        __syncthreads();
        if (tid < 128) C[bm + tid] = simS[tid] * (1.f / 2048.f);
        return;
    }

    #pragma unroll
    for (int mt = 0; mt < 4; mt++) {
        int row = bm + wm * 64 + mt * 16 + lr;
        #pragma unroll
        for (int nt = 0; nt < 4; nt++) {
            int col = bn + wn * 32 + nt * 8 + 2 * lc;
            float2 b2 = *(const float2*)(bias + col);
            float v0 = acc[mt][nt][0] + b2.x;
            float v1 = acc[mt][nt][1] + b2.y;
            float v2 = acc[mt][nt][2] + b2.x;
            float v3 = acc[mt][nt][3] + b2.y;
            if (mode == EP_RES) {
                float2 r0 = *(const float2*)(R + (size_t)row * ldc + col);
                float2 r1 = *(const float2*)(R + (size_t)(row + 8) * ldc + col);
                v0 += r0.x; v1 += r0.y; v2 += r1.x; v3 += r1.y;
            } else if (mode == EP_GELU) {
                v0 = gelu_f(v0); v1 = gelu_f(v1); v2 = gelu_f(v2); v3 = gelu_f(v3);
            } else if (mode == EP_FINAL) {
                float2 r0 = *(const float2*)(R + (size_t)row * ldc + col);
                float2 r1 = *(const float2*)(R + (size_t)(row + 8) * ldc + col);
                float sc0 = rs[row], sc1 = rs[row + 8];
                v0 = r0.x + sc0 * v0; v1 = r0.y + sc0 * v1;
                v2 = r1.x + sc1 * v2; v3 = r1.y + sc1 * v3;
            }
            float2 o0 = make_float2(v0, v1), o1 = make_float2(v2, v3);
            *(float2*)(C + (size_t)row * ldc + col) = o0;
            *(float2*)(C + (size_t)(row + 8) * ldc + col) = o1;
        }
    }
}

// smem byte offsets for mcov: 32 rows (s) x 136 bf16 (272B stride) per buffer
#define CS_H 0
#define CS_L 8704
#define CT_H 17408
#define CT_L 26112
#define CSM_TOT 34816

// ========== M covariance: M[b][d][e] += sum_s sn[b,s,d] * tn[b,s,e] ==========
// grid (8 splits, 8 batches), 256 threads. Both operands via ldmatrix.trans.
__global__ void __launch_bounds__(256) mcov_mma(
    const float* __restrict__ sn, const float* __restrict__ tn, float* __restrict__ M)
{
    extern __shared__ char smem[];
    uint32_t sb = smem_to_u32(smem);
    const int tid = threadIdx.x, lane = tid & 31, wid = tid >> 5;
    const int wm = wid >> 2, wn = wid & 3;
    const int lr = lane >> 2, lc = lane & 3;
    const int b = blockIdx.y, split = blockIdx.x;

    const int r = tid >> 3, q = tid & 7;
    const size_t srow0 = (size_t)b * SS + split * 256;
    const float* Sp = sn + (srow0 + r) * 128 + q * 16;
    const float* Tp = tn + (srow0 + r) * 128 + q * 16;
    char* stS = smem + r * 272 + q * 32;
    char* stT = smem + CT_H + r * 272 + q * 32;

    float acc[4][4][4];
    #pragma unroll
    for (int i = 0; i < 4; i++)
        #pragma unroll
        for (int j = 0; j < 4; j++)
            #pragma unroll
            for (int k = 0; k < 4; k++) acc[i][j][k] = 0.f;

    float4 ps[4], pt[4];
    #pragma unroll
    for (int i = 0; i < 4; i++) {
        ps[i] = *(const float4*)(Sp + i * 4);
        pt[i] = *(const float4*)(Tp + i * 4);
    }

    for (int c = 0; c < 8; c++) {
        #pragma unroll
        for (int i = 0; i < 4; i++) {
            uint2 hv, lv;
            cvt_split4(ps[i], hv, lv);
            *(uint2*)(stS + i * 8) = hv;
            *(uint2*)(stS + CS_L + i * 8) = lv;
            cvt_split4(pt[i], hv, lv);
            *(uint2*)(stT + i * 8) = hv;
            *(uint2*)(stT + CS_L + i * 8) = lv;
        }
        __syncthreads();
        if (c + 1 < 8) {
            #pragma unroll
            for (int i = 0; i < 4; i++) {
                ps[i] = *(const float4*)(Sp + (size_t)(c + 1) * 32 * 128 + i * 4);
                pt[i] = *(const float4*)(Tp + (size_t)(c + 1) * 32 * 128 + i * 4);
            }
        }
        #pragma unroll
        for (int ks = 0; ks < 2; ks++) {
            uint32_t ah[4][4], al[4][4], bh[4][2], bl[4][2];
            #pragma unroll
            for (int mt = 0; mt < 4; mt++) {
                int rowk = ks * 16 + (lane & 7) + ((lane >> 4) & 1) * 8;
                int colm = wm * 64 + mt * 16 + ((lane >> 3) & 1) * 8;
                uint32_t addr = sb + CS_H + (uint32_t)(rowk * 272 + colm * 2);
                LDSM4T(ah[mt][0], ah[mt][1], ah[mt][2], ah[mt][3], addr);
                LDSM4T(al[mt][0], al[mt][1], al[mt][2], al[mt][3], addr + CS_L);
            }
            #pragma unroll
            for (int nt = 0; nt < 4; nt++) {
                int rowk = ks * 16 + (lane & 15);
                int coln = wn * 32 + nt * 8;
                uint32_t addr = sb + CT_H + (uint32_t)(rowk * 272 + coln * 2);
                LDSM2T(bh[nt][0], bh[nt][1], addr);
                LDSM2T(bl[nt][0], bl[nt][1], addr + CS_L);
            }
            #pragma unroll
            for (int mt = 0; mt < 4; mt++)
                #pragma unroll
                for (int nt = 0; nt < 4; nt++) {
                    MMA_BF16(acc[mt][nt], ah[mt], bh[nt]);
                    MMA_BF16(acc[mt][nt], ah[mt], bl[nt]);
                    MMA_BF16(acc[mt][nt], al[mt], bh[nt]);
                }
        }
        __syncthreads();
    }

    float* Mb = M + (size_t)b * 16384;
    #pragma unroll
    for (int mt = 0; mt < 4; mt++) {
        int row = wm * 64 + mt * 16 + lr;
        #pragma unroll
        for (int nt = 0; nt < 4; nt++) {
            int col = wn * 32 + nt * 8 + 2 * lc;
            atomicAdd(&Mb[(size_t)row * 128 + col], acc[mt][nt][0]);
            atomicAdd(&Mb[(size_t)row * 128 + col + 1], acc[mt][nt][1]);
            atomicAdd(&Mb[(size_t)(row + 8) * 128 + col], acc[mt][nt][2]);
            atomicAdd(&Mb[(size_t)(row + 8) * 128 + col + 1], acc[mt][nt][3]);
        }
    }
}

// ---------------- local windowed causal attention ----------------
__global__ __launch_bounds__(64) void lw_attn_k(const float* __restrict__ qkv,
                                                float* __restrict__ out)
{
    int g = blockIdx.x, h = blockIdx.y, i = threadIdx.x;
    __shared__ float ks[64][17];
    __shared__ float vs[64][17];
    size_t tbase = (size_t)g * 64;
    const float* kp = qkv + (tbase + i) * 384 + 128 + h * 16;
    const float* vp = kp + 128;
    #pragma unroll
    for (int d = 0; d < 16; d++) { ks[i][d] = kp[d]; vs[i][d] = vp[d]; }
    float q[16];
    const float* qp = qkv + (tbase + i) * 384 + h * 16;
    #pragma unroll
    for (int d = 0; d < 16; d++) q[d] = qp[d];
    __syncthreads();
    float sc[64];
    float mx = -1e30f;
    #pragma unroll
    for (int j = 0; j < 64; j++) {
        float dv = 0.f;
        #pragma unroll
        for (int d = 0; d < 16; d++) dv += q[d] * ks[j][d];
        sc[j] = (j <= i) ? dv * 0.25f : -INFINITY;
        mx = fmaxf(mx, sc[j]);
    }
    float sum = 0.f;
    #pragma unroll
    for (int j = 0; j < 64; j++) { float e = expf(sc[j] - mx); sc[j] = e; sum += e; }
    float o[16] = {};
    #pragma unroll
    for (int j = 0; j < 64; j++) {
        float w = sc[j];
        #pragma unroll
        for (int d = 0; d < 16; d++) o[d] += w * vs[j][d];
    }
    float inv = 1.f / sum;
    float* op = out + (tbase + i) * 128 + h * 16;
    #pragma unroll
    for (int d = 0; d < 16; d++) op[d] = o[d] * inv;
}

// ---------------- interaction MHA (len = B = 8) ----------------
__global__ __launch_bounds__(64) void int_attn_k(const float* __restrict__ qkv,
                                                 float* __restrict__ out)
{
    int s = blockIdx.x, tid = threadIdx.x;
    __shared__ float kvs[8][256];
    for (int idx = tid; idx < 8 * 256; idx += 64) {
        int jb = idx >> 8, c = idx & 255;
        kvs[jb][c] = qkv[((size_t)jb * SS + s) * 384 + 128 + c];
    }
    __syncthreads();
    int h = tid >> 3, qb = tid & 7;
    float q[16];
    const float* qp = qkv + ((size_t)qb * SS + s) * 384 + h * 16;
    #pragma unroll
    for (int d = 0; d < 16; d++) q[d] = qp[d];
    float sc[8];
    float mx = -1e30f;
    #pragma unroll
    for (int jb = 0; jb < 8; jb++) {
        float dv = 0.f;
        #pragma unroll
        for (int d = 0; d < 16; d++) dv += q[d] * kvs[jb][h * 16 + d];
        sc[jb] = dv * 0.25f;
        mx = fmaxf(mx, sc[jb]);
    }
    float sum = 0.f;
    #pragma unroll
    for (int jb = 0; jb < 8; jb++) { float e = expf(sc[jb] - mx); sc[jb] = e; sum += e; }
    float o[16] = {};
    #pragma unroll
    for (int jb = 0; jb < 8; jb++) {
        float w = sc[jb];
        #pragma unroll
        for (int d = 0; d < 16; d++) o[d] += w * kvs[jb][128 + h * 16 + d];
    }
    float inv = 1.f / sum;
    float* op = out + ((size_t)qb * SS + s) * 128 + h * 16;
    #pragma unroll
    for (int d = 0; d < 16; d++) op[d] = o[d] * inv;
}

// ---------------- LayerNorm, warp per token, float4 ----------------
__global__ __launch_bounds__(256) void ln_k(float* __restrict__ x,
                                            const float* __restrict__ g,
                                            const float* __restrict__ b)
{
    int w = threadIdx.x >> 5, lane = threadIdx.x & 31;
    size_t t = (size_t)blockIdx.x * 8 + w;
    float4 v = *(float4*)(x + t * 128 + lane * 4);
    float s = v.x + v.y + v.z + v.w;
    float s2 = v.x * v.x + v.y * v.y + v.z * v.z + v.w * v.w;
    #pragma unroll
    for (int o = 16; o; o >>= 1) {
        s += __shfl_xor_sync(0xffffffffu, s, o);
        s2 += __shfl_xor_sync(0xffffffffu, s2, o);
    }
    float mu = s * (1.f / 128.f);
    float var = s2 * (1.f / 128.f) - mu * mu;
    float rf = rsqrtf(var + 1e-5f);
    float4 g4 = *(const float4*)(g + lane * 4);
    float4 b4 = *(const float4*)(b + lane * 4);
    v.x = (v.x - mu) * rf * g4.x + b4.x;
    v.y = (v.y - mu) * rf * g4.y + b4.y;
    v.z = (v.z - mu) * rf * g4.z + b4.z;
    v.w = (v.w - mu) * rf * g4.w + b4.w;
    *(float4*)(x + t * 128 + lane * 4) = v;
}

// ---------------- cosine normalize, warp per token ----------------
__global__ __launch_bounds__(256) void cosnorm_k(const float* __restrict__ e,
                                                 float* __restrict__ o)
{
    int w = threadIdx.x >> 5, lane = threadIdx.x & 31;
    size_t t = (size_t)blockIdx.x * 8 + w;
    float4 v = *(const float4*)(e + t * 128 + lane * 4);
    float s2 = v.x * v.x + v.y * v.y + v.z * v.z + v.w * v.w;
    #pragma unroll
    for (int off = 16; off; off >>= 1) s2 += __shfl_xor_sync(0xffffffffu, s2, off);
    float inv = 1.f / fmaxf(sqrtf(s2), 1e-8f);
    v.x *= inv; v.y *= inv; v.z *= inv; v.w *= inv;
    *(float4*)(o + t * 128 + lane * 4) = v;
}

__global__ void zero_k(float* p, int n)
{
    int i = blockIdx.x * 256 + threadIdx.x;
    if (i < n) p[i] = 0.f;
}

extern "C" void kernel_launch(void* const* d_in, const int* in_sizes, int n_in,
                              void* d_out, int out_size)
{
    const float* x        = (const float*)d_in[0];
    const float* sp       = (const float*)d_in[1];
    const float* tp       = (const float*)d_in[2];
    const float* lw_in_w  = (const float*)d_in[3];
    const float* lw_in_b  = (const float*)d_in[4];
    const float* lw_out_w = (const float*)d_in[5];
    const float* lw_out_b = (const float*)d_in[6];
    const float* spat_w   = (const float*)d_in[7];
    const float* spat_b   = (const float*)d_in[8];
    const float* temp_w   = (const float*)d_in[9];
    const float* temp_b   = (const float*)d_in[10];
    const float* int_in_w = (const float*)d_in[11];
    const float* int_in_b = (const float*)d_in[12];
    const float* int_out_w= (const float*)d_in[13];
    const float* int_out_b= (const float*)d_in[14];
    const float* ffn_w1   = (const float*)d_in[15];
    const float* ffn_b1   = (const float*)d_in[16];
    const float* ffn_w2   = (const float*)d_in[17];
    const float* ffn_b2   = (const float*)d_in[18];
    const float* ln1_g    = (const float*)d_in[19];
    const float* ln1_b    = (const float*)d_in[20];
    const float* ln2_g    = (const float*)d_in[21];
    const float* ln2_b    = (const float*)d_in[22];
    float* out = (float*)d_out;

    float* scr = nullptr;
    cudaGetSymbolAddress((void**)&scr, g_scr);
    float* qkv  = scr + OFF_QKV;
    float* bufa = scr + OFF_A;
    float* bufb = scr + OFF_B;
    float* bufh = scr + OFF_H;
    float* bufc = scr + OFF_C;
    float* bse  = scr + OFF_SE;
    float* bte  = scr + OFF_TE;
    float* bsn  = scr + OFF_SN;
    float* btn  = scr + OFF_TN;
    float* bM   = scr + OFF_M;
    float* bsim = scr + OFF_SIM;

    // --- local window attention path ---
    gemm_mma<<<dim3(3, 128), 256, GSM_TOT>>>(x, lw_in_w, lw_in_b, qkv, nullptr, nullptr, 128, 384, EP_BIAS, 0);
    lw_attn_k<<<dim3(256, 8), 64>>>(qkv, bufa);
    gemm_mma<<<dim3(1, 128), 256, GSM_TOT>>>(bufa, lw_out_w, lw_out_b, bufb, x, nullptr, 128, 128, EP_RES, 0);
    ln_k<<<2048, 256>>>(bufb, ln1_g, ln1_b);
    // --- FFN ---
    gemm_mma<<<dim3(4, 128), 256, GSM_TOT>>>(bufb, ffn_w1, ffn_b1, bufh, nullptr, nullptr, 128, 512, EP_GELU, 0);
    gemm_mma<<<dim3(1, 128), 256, GSM_TOT>>>(bufh, ffn_w2, ffn_b2, bufc, bufb, nullptr, 512, 128, EP_RES, 0);
    ln_k<<<2048, 256>>>(bufc, ln2_g, ln2_b);
    // --- spatio-temporal embeddings ---
    gemm_mma<<<dim3(1, 128), 256, GSM_TOT>>>(sp, spat_w, spat_b, bse, nullptr, nullptr, 128, 128, EP_BIAS, 0);
    gemm_mma<<<dim3(1, 128), 256, GSM_TOT>>>(tp, temp_w, temp_b, bte, nullptr, nullptr, 128, 128, EP_BIAS, 0);
    cosnorm_k<<<2048, 256>>>(bse, bsn);
    cosnorm_k<<<2048, 256>>>(bte, btn);
    // --- sim via M factorization: M_b = sn^T tn; sim = (1/S) sn^T (M tn) ---
    zero_k<<<512, 256>>>(bM, 8 * 128 * 128);
    mcov_mma<<<dim3(8, 8), 256, CSM_TOT>>>(bsn, btn, bM);
    gemm_mma<<<dim3(1, 128), 256, GSM_TOT>>>(btn, bM, nullptr, bsim, bsn, nullptr, 128, 0, EP_SIMDOT, 16384);
    // --- interaction MHA (len = B = 8) ---
    gemm_mma<<<dim3(1, 128), 256, GSM_TOT>>>(bse, int_in_w, int_in_b, qkv, nullptr, nullptr, 128, 384, EP_BIAS, 0);
    gemm_mma<<<dim3(2, 128), 256, GSM_TOT>>>(bte, int_in_w + 128 * 128, int_in_b + 128, qkv + 128,
                                             nullptr, nullptr, 128, 384, EP_BIAS, 0);
    int_attn_k<<<SS, 64>>>(qkv, bufa);
    // --- final: out = x2 + sim[t] * (attn @ Wout^T + bout) ---
    gemm_mma<<<dim3(1, 128), 256, GSM_TOT>>>(bufa, int_out_w, int_out_b, out, bufc, bsim, 128, 128, EP_FINAL, 0);
}

// round 4
// speedup vs baseline: 2.1195x; 1.4307x over previous
#include <cuda_runtime.h>
#include <cuda_bf16.h>
#include <cstdint>
#include <math.h>

#define BB 8
#define SS 2048
#define TT 16384

// ---------------- float scratch ----------------
#define F_QKV  0u          // 16384*384
#define F_BUFB 6291456u    // 16384*128
#define F_BUFC 8388608u
#define F_SNF  10485760u
#define F_M    12582912u   // 8*128*128
#define F_SIM  12713984u   // 16384
#define F_TOT  12730368u
__device__ float g_f32[F_TOT];

// ---------------- bf16 scratch (each tensor: HI then LO contiguous) ----------------
#define H_X      0u
#define H_SP     4194304u
#define H_TP     8388608u
#define H_ATT    12582912u
#define H_BUFB   16777216u
#define H_BUFH   20971520u   // 16384*512 *2
#define H_SE     37748736u
#define H_SN     41943040u
#define H_TE     46137344u
#define H_TN     50331648u
#define H_M      54525952u   // 131072*2
#define H_LWIN   54788096u   // 49152*2
#define H_LWOUT  54886400u   // 16384*2
#define H_SPATW  54919168u
#define H_TEMPW  54951936u
#define H_INTIN  54984704u   // 49152*2
#define H_INTOUT 55083008u
#define H_FW1    55115776u   // 65536*2
#define H_FW2    55246848u
#define BF_TOT   55377920u
__device__ __nv_bfloat16 g_bf[BF_TOT];

enum { EP_F32 = 0, EP_LN = 1, EP_GELU = 2, EP_LN2 = 3, EP_COS = 4, EP_FINAL = 5, EP_SIMDOT = 6 };

__device__ __forceinline__ uint32_t smem_to_u32(const void* p) {
    uint32_t a;
    asm("{ .reg .u64 t; cvta.to.shared.u64 t, %1; cvt.u32.u64 %0, t; }" : "=r"(a) : "l"(p));
    return a;
}

#define CP16(dst, src) do { \
    unsigned long long _gs = (unsigned long long)__cvta_generic_to_global((const void*)(src)); \
    asm volatile("cp.async.cg.shared.global [%0], [%1], 16;" :: "r"(dst), "l"(_gs)); } while (0)
#define CP_COMMIT() asm volatile("cp.async.commit_group;" ::: "memory")
#define CP_WAIT(n) asm volatile("cp.async.wait_group %0;" :: "n"(n) : "memory")

#define LDSM4(r0, r1, r2, r3, addr) \
    asm volatile("ldmatrix.sync.aligned.m8n8.x4.shared.b16 {%0,%1,%2,%3}, [%4];" \
        : "=r"(r0), "=r"(r1), "=r"(r2), "=r"(r3) : "r"(addr))
#define LDSM4T(r0, r1, r2, r3, addr) \
    asm volatile("ldmatrix.sync.aligned.m8n8.x4.trans.shared.b16 {%0,%1,%2,%3}, [%4];" \
        : "=r"(r0), "=r"(r1), "=r"(r2), "=r"(r3) : "r"(addr))
#define LDSM2(r0, r1, addr) \
    asm volatile("ldmatrix.sync.aligned.m8n8.x2.shared.b16 {%0,%1}, [%2];" \
        : "=r"(r0), "=r"(r1) : "r"(addr))
#define LDSM2T(r0, r1, addr) \
    asm volatile("ldmatrix.sync.aligned.m8n8.x2.trans.shared.b16 {%0,%1}, [%2];" \
        : "=r"(r0), "=r"(r1) : "r"(addr))

#define MMA_BF16(c, a, b) \
    asm volatile("mma.sync.aligned.m16n8k16.row.col.f32.bf16.bf16.f32 " \
        "{%0,%1,%2,%3}, {%4,%5,%6,%7}, {%8,%9}, {%0,%1,%2,%3};" \
        : "+f"((c)[0]), "+f"((c)[1]), "+f"((c)[2]), "+f"((c)[3]) \
        : "r"((a)[0]), "r"((a)[1]), "r"((a)[2]), "r"((a)[3]), "r"((b)[0]), "r"((b)[1]))

__device__ __forceinline__ void cvt_split4(float4 v, uint2& hv, uint2& lv) {
    __nv_bfloat16 h0 = __float2bfloat16_rn(v.x);
    __nv_bfloat16 h1 = __float2bfloat16_rn(v.y);
    __nv_bfloat16 h2 = __float2bfloat16_rn(v.z);
    __nv_bfloat16 h3 = __float2bfloat16_rn(v.w);
    __nv_bfloat16 l0 = __float2bfloat16_rn(v.x - __bfloat162float(h0));
    __nv_bfloat16 l1 = __float2bfloat16_rn(v.y - __bfloat162float(h1));
    __nv_bfloat16 l2 = __float2bfloat16_rn(v.z - __bfloat162float(h2));
    __nv_bfloat16 l3 = __float2bfloat16_rn(v.w - __bfloat162float(h3));
    hv.x = (uint32_t)__bfloat16_as_ushort(h0) | ((uint32_t)__bfloat16_as_ushort(h1) << 16);
    hv.y = (uint32_t)__bfloat16_as_ushort(h2) | ((uint32_t)__bfloat16_as_ushort(h3) << 16);
    lv.x = (uint32_t)__bfloat16_as_ushort(l0) | ((uint32_t)__bfloat16_as_ushort(l1) << 16);
    lv.y = (uint32_t)__bfloat16_as_ushort(l2) | ((uint32_t)__bfloat16_as_ushort(l3) << 16);
}

__device__ __forceinline__ void store_hl(__nv_bfloat16* Ch, __nv_bfloat16* Cl,
                                         size_t idx, float w0, float w1) {
    __nv_bfloat16 h0 = __float2bfloat16_rn(w0), h1 = __float2bfloat16_rn(w1);
    __nv_bfloat162 hp; hp.x = h0; hp.y = h1;
    *(__nv_bfloat162*)(Ch + idx) = hp;
    __nv_bfloat162 lp;
    lp.x = __float2bfloat16_rn(w0 - __bfloat162float(h0));
    lp.y = __float2bfloat16_rn(w1 - __bfloat162float(h1));
    *(__nv_bfloat162*)(Cl + idx) = lp;
}

__device__ __forceinline__ float gelu_f(float v) {
    return 0.5f * v * (1.0f + erff(v * 0.70710678118654752f));
}

// ============== pre-split conversion of inputs/weights ==============
struct CvtSrc { const float* p[11]; };
__global__ void __launch_bounds__(256) cvt_all_k(CvtSrc s)
{
    const int ns[11] = {2097152, 2097152, 2097152, 49152, 16384, 16384, 16384,
                        49152, 16384, 65536, 65536};
    const unsigned offs[11] = {H_X, H_SP, H_TP, H_LWIN, H_LWOUT, H_SPATW, H_TEMPW,
                               H_INTIN, H_INTOUT, H_FW1, H_FW2};
    int stride = gridDim.x * blockDim.x;
    int t = blockIdx.x * blockDim.x + threadIdx.x;
    for (int seg = 0; seg < 11; seg++) {
        const float4* src = (const float4*)s.p[seg];
        __nv_bfloat16* dh = g_bf + offs[seg];
        __nv_bfloat16* dl = dh + ns[seg];
        int m = ns[seg] >> 2;
        for (int i = t; i < m; i += stride) {
            uint2 hv, lv;
            cvt_split4(src[i], hv, lv);
            *(uint2*)(dh + (size_t)i * 4) = hv;
            *(uint2*)(dl + (size_t)i * 4) = lv;
        }
    }
}

__global__ void __launch_bounds__(256) cvtm_k(const float* __restrict__ src,
                                              __nv_bfloat16* dh, __nv_bfloat16* dl, int n)
{
    int t = blockIdx.x * blockDim.x + threadIdx.x;
    int m = n >> 2;
    for (int i = t; i < m; i += gridDim.x * blockDim.x) {
        uint2 hv, lv;
        cvt_split4(((const float4*)src)[i], hv, lv);
        *(uint2*)(dh + (size_t)i * 4) = hv;
        *(uint2*)(dl + (size_t)i * 4) = lv;
    }
}

__global__ void zero_k(float* p, int n)
{
    int i = blockIdx.x * 256 + threadIdx.x;
    if (i < n) p[i] = 0.f;
}

// ============== generic bf16-split GEMM: C[M,N] = A @ W^T ==============
// smem: stage s at s*40960: AH +0, AL +10240, WH +20480, WL +30720 (128 rows x 80B)
#define GST 40960
__global__ void __launch_bounds__(256) gemm_mma(
    const __nv_bfloat16* __restrict__ Ah, const __nv_bfloat16* __restrict__ Al,
    const __nv_bfloat16* __restrict__ A2h, const __nv_bfloat16* __restrict__ A2l,
    const __nv_bfloat16* __restrict__ Wh, const __nv_bfloat16* __restrict__ Wl,
    const float* __restrict__ bias, float* __restrict__ C,
    __nv_bfloat16* __restrict__ Ch, __nv_bfloat16* __restrict__ Cl,
    __nv_bfloat16* __restrict__ C2h, __nv_bfloat16* __restrict__ C2l,
    const float* __restrict__ R, const float* __restrict__ rs,
    const float* __restrict__ gam, const float* __restrict__ bet,
    int K, int ldc, int mode, int batchW)
{
    extern __shared__ char smem[];
    uint32_t sb = smem_to_u32(smem);
    const int tid = threadIdx.x, lane = tid & 31, wid = tid >> 5;
    const int wm = wid >> 2, wn = wid & 3;
    const int lr = lane >> 2, lc = lane & 3;
    const int bm = blockIdx.y * 128, bn = blockIdx.x * 128;

    const __nv_bfloat16* Auh = (A2h && bn > 0) ? A2h : Ah;
    const __nv_bfloat16* Aul = (A2h && bn > 0) ? A2l : Al;
    if (batchW) { Wh += (size_t)(bm >> 11) * (size_t)batchW; Wl += (size_t)(bm >> 11) * (size_t)batchW; }

    const int r = tid >> 1, half = tid & 1;
    const size_t aIdx = (size_t)(bm + r) * K + half * 16;
    const size_t wIdx = (size_t)(bn + r) * K + half * 16;
    const __nv_bfloat16 *pAh = Auh + aIdx, *pAl = Aul + aIdx;
    const __nv_bfloat16 *pWh = Wh + wIdx, *pWl = Wl + wIdx;
    const uint32_t dBase = sb + r * 80 + half * 32;

    float acc[4][4][4];
    #pragma unroll
    for (int i = 0; i < 4; i++)
        #pragma unroll
        for (int j = 0; j < 4; j++)
            #pragma unroll
            for (int k = 0; k < 4; k++) acc[i][j][k] = 0.f;

    const int nch = K >> 5;

    // prologue: chunk 0 into stage 0
    {
        uint32_t d = dBase;
        CP16(d, pAh); CP16(d + 16, pAh + 8);
        CP16(d + 10240, pAl); CP16(d + 10240 + 16, pAl + 8);
        CP16(d + 20480, pWh); CP16(d + 20480 + 16, pWh + 8);
        CP16(d + 30720, pWl); CP16(d + 30720 + 16, pWl + 8);
        CP_COMMIT();
    }

    for (int c = 0; c < nch; c++) {
        if (c + 1 < nch) {
            uint32_t d = dBase + ((c + 1) & 1) * GST;
            const int co = (c + 1) * 32;
            CP16(d, pAh + co); CP16(d + 16, pAh + co + 8);
            CP16(d + 10240, pAl + co); CP16(d + 10240 + 16, pAl + co + 8);
            CP16(d + 20480, pWh + co); CP16(d + 20480 + 16, pWh + co + 8);
            CP16(d + 30720, pWl + co); CP16(d + 30720 + 16, pWl + co + 8);
            CP_COMMIT();
            CP_WAIT(1);
        } else {
            CP_WAIT(0);
        }
        __syncthreads();
        uint32_t base = sb + (c & 1) * GST;
        #pragma unroll
        for (int ks = 0; ks < 2; ks++) {
            uint32_t ah[4][4], al[4][4], bh[4][2], bl[4][2];
            #pragma unroll
            for (int mt = 0; mt < 4; mt++) {
                uint32_t addr = base + (uint32_t)((wm * 64 + mt * 16 + (lane & 15)) * 80
                               + ks * 32 + ((lane >> 4) & 1) * 16);
                LDSM4(ah[mt][0], ah[mt][1], ah[mt][2], ah[mt][3], addr);
                LDSM4(al[mt][0], al[mt][1], al[mt][2], al[mt][3], addr + 10240);
            }
            #pragma unroll
            for (int nt = 0; nt < 4; nt++) {
                uint32_t addr = base + 20480 + (uint32_t)((wn * 32 + nt * 8 + (lane & 7)) * 80
                               + ks * 32 + ((lane >> 3) & 1) * 16);
                LDSM2(bh[nt][0], bh[nt][1], addr);
                LDSM2(bl[nt][0], bl[nt][1], addr + 10240);
            }
            #pragma unroll
            for (int mt = 0; mt < 4; mt++)
                #pragma unroll
                for (int nt = 0; nt < 4; nt++) {
                    MMA_BF16(acc[mt][nt], ah[mt], bh[nt]);
                    MMA_BF16(acc[mt][nt], ah[mt], bl[nt]);
                    MMA_BF16(acc[mt][nt], al[mt], bh[nt]);
                }
        }
        __syncthreads();
    }

    // ---------------- epilogues ----------------
    if (mode == EP_SIMDOT) {
        float* simS = (float*)smem;
        if (tid < 128) simS[tid] = 0.f;
        __syncthreads();
        #pragma unroll
        for (int mt = 0; mt < 4; mt++) {
            int row0 = bm + wm * 64 + mt * 16 + lr;
            float d0 = 0.f, d1 = 0.f;
            #pragma unroll
            for (int nt = 0; nt < 4; nt++) {
                int col = bn + wn * 32 + nt * 8 + 2 * lc;
                float2 s0 = *(const float2*)(R + (size_t)row0 * 128 + col);
                float2 s1 = *(const float2*)(R + (size_t)(row0 + 8) * 128 + col);
                d0 += acc[mt][nt][0] * s0.x + acc[mt][nt][1] * s0.y;
                d1 += acc[mt][nt][2] * s1.x + acc[mt][nt][3] * s1.y;
            }
            d0 += __shfl_xor_sync(0xffffffffu, d0, 1);
            d0 += __shfl_xor_sync(0xffffffffu, d0, 2);
            d1 += __shfl_xor_sync(0xffffffffu, d1, 1);
            d1 += __shfl_xor_sync(0xffffffffu, d1, 2);
            if (lc == 0) {
                atomicAdd(&simS[wm * 64 + mt * 16 + lr], d0);
                atomicAdd(&simS[wm * 64 + mt * 16 + lr + 8], d1);
            }
        }
        __syncthreads();
        if (tid < 128) C[bm + tid] = simS[tid] * (1.f / 2048.f);
        return;
    }

    // bias + per-mode pre-transform (in place in acc)
    #pragma unroll
    for (int mt = 0; mt < 4; mt++) {
        int row = bm + wm * 64 + mt * 16 + lr;
        #pragma unroll
        for (int nt = 0; nt < 4; nt++) {
            int col = bn + wn * 32 + nt * 8 + 2 * lc;
            float2 b2 = *(const float2*)(bias + col);
            float* a = acc[mt][nt];
            a[0] += b2.x; a[1] += b2.y; a[2] += b2.x; a[3] += b2.y;
            if (mode == EP_LN || mode == EP_LN2) {
                float2 r0 = *(const float2*)(R + (size_t)row * ldc + col);
                float2 r1 = *(const float2*)(R + (size_t)(row + 8) * ldc + col);
                a[0] += r0.x; a[1] += r0.y; a[2] += r1.x; a[3] += r1.y;
            } else if (mode == EP_GELU) {
                a[0] = gelu_f(a[0]); a[1] = gelu_f(a[1]);
                a[2] = gelu_f(a[2]); a[3] = gelu_f(a[3]);
            } else if (mode == EP_FINAL) {
                float2 r0 = *(const float2*)(R + (size_t)row * ldc + col);
                float2 r1 = *(const float2*)(R + (size_t)(row + 8) * ldc + col);
                float sc0 = rs[row], sc1 = rs[row + 8];
                a[0] = r0.x + sc0 * a[0]; a[1] = r0.y + sc0 * a[1];
                a[2] = r1.x + sc1 * a[2]; a[3] = r1.y + sc1 * a[3];
            }
        }
    }

    if (mode == EP_LN || mode == EP_LN2 || mode == EP_COS) {
        float* ps = (float*)smem;
        float* ps2 = ps + 512;
        #pragma unroll
        for (int mt = 0; mt < 4; mt++) {
            float p0 = 0.f, p1 = 0.f, q0 = 0.f, q1 = 0.f;
            #pragma unroll
            for (int nt = 0; nt < 4; nt++) {
                float* a = acc[mt][nt];
                p0 += a[0] + a[1]; q0 += a[0] * a[0] + a[1] * a[1];
                p1 += a[2] + a[3]; q1 += a[2] * a[2] + a[3] * a[3];
            }
            p0 += __shfl_xor_sync(0xffffffffu, p0, 1); p0 += __shfl_xor_sync(0xffffffffu, p0, 2);
            p1 += __shfl_xor_sync(0xffffffffu, p1, 1); p1 += __shfl_xor_sync(0xffffffffu, p1, 2);
            q0 += __shfl_xor_sync(0xffffffffu, q0, 1); q0 += __shfl_xor_sync(0xffffffffu, q0, 2);
            q1 += __shfl_xor_sync(0xffffffffu, q1, 1); q1 += __shfl_xor_sync(0xffffffffu, q1, 2);
            if (lc == 0) {
                int r0l = wm * 64 + mt * 16 + lr;
                ps[r0l * 4 + wn] = p0; ps2[r0l * 4 + wn] = q0;
                ps[(r0l + 8) * 4 + wn] = p1; ps2[(r0l + 8) * 4 + wn] = q1;
            }
        }
        __syncthreads();
        #pragma unroll
        for (int mt = 0; mt < 4; mt++) {
            int r0l = wm * 64 + mt * 16 + lr;
            float s0 = 0.f, t0 = 0.f, s1 = 0.f, t1 = 0.f;
            #pragma unroll
            for (int w4 = 0; w4 < 4; w4++) {
                s0 += ps[r0l * 4 + w4]; t0 += ps2[r0l * 4 + w4];
                s1 += ps[(r0l + 8) * 4 + w4]; t1 += ps2[(r0l + 8) * 4 + w4];
            }
            int row0 = bm + r0l;
            if (mode == EP_COS) {
                float i0 = 1.f / fmaxf(sqrtf(t0), 1e-8f);
                float i1 = 1.f / fmaxf(sqrtf(t1), 1e-8f);
                #pragma unroll
                for (int nt = 0; nt < 4; nt++) {
                    int col = bn + wn * 32 + nt * 8 + 2 * lc;
                    float* a = acc[mt][nt];
                    size_t i0x = (size_t)row0 * ldc + col, i1x = (size_t)(row0 + 8) * ldc + col;
                    store_hl(Ch, Cl, i0x, a[0], a[1]);
                    store_hl(Ch, Cl, i1x, a[2], a[3]);
                    float n0 = a[0] * i0, n1 = a[1] * i0, n2 = a[2] * i1, n3 = a[3] * i1;
                    store_hl(C2h, C2l, i0x, n0, n1);
                    store_hl(C2h, C2l, i1x, n2, n3);
                    if (C) {
                        *(float2*)(C + i0x) = make_float2(n0, n1);
                        *(float2*)(C + i1x) = make_float2(n2, n3);
                    }
                }
            } else {
                float mu0 = s0 * (1.f / 128.f), mu1 = s1 * (1.f / 128.f);
                float rs0 = rsqrtf(t0 * (1.f / 128.f) - mu0 * mu0 + 1e-5f);
                float rs1 = rsqrtf(t1 * (1.f / 128.f) - mu1 * mu1 + 1e-5f);
                #pragma unroll
                for (int nt = 0; nt < 4; nt++) {
                    int col = bn + wn * 32 + nt * 8 + 2 * lc;
                    float* a = acc[mt][nt];
                    float2 g2 = *(const float2*)(gam + col);
                    float2 be2 = *(const float2*)(bet + col);
                    float w0 = (a[0] - mu0) * rs0 * g2.x + be2.x;
                    float w1 = (a[1] - mu0) * rs0 * g2.y + be2.y;
                    float w2 = (a[2] - mu1) * rs1 * g2.x + be2.x;
                    float w3 = (a[3] - mu1) * rs1 * g2.y + be2.y;
                    size_t i0x = (size_t)row0 * ldc + col, i1x = (size_t)(row0 + 8) * ldc + col;
                    *(float2*)(C + i0x) = make_float2(w0, w1);
                    *(float2*)(C + i1x) = make_float2(w2, w3);
                    if (Ch) {
                        store_hl(Ch, Cl, i0x, w0, w1);
                        store_hl(Ch, Cl, i1x, w2, w3);
                    }
                }
            }
        }
    } else {
        // EP_F32 / EP_FINAL / EP_GELU
        #pragma unroll
        for (int mt = 0; mt < 4; mt++) {
            int row = bm + wm * 64 + mt * 16 + lr;
            #pragma unroll
            for (int nt = 0; nt < 4; nt++) {
                int col = bn + wn * 32 + nt * 8 + 2 * lc;
                float* a = acc[mt][nt];
                size_t i0x = (size_t)row * ldc + col, i1x = (size_t)(row + 8) * ldc + col;
                if (mode == EP_GELU) {
                    store_hl(Ch, Cl, i0x, a[0], a[1]);
                    store_hl(Ch, Cl, i1x, a[2], a[3]);
                } else {
                    *(float2*)(C + i0x) = make_float2(a[0], a[1]);
                    *(float2*)(C + i1x) = make_float2(a[2], a[3]);
                }
            }
        }
    }
}

// ============== M covariance: M[b] += sn^T tn (contract over s) ==============
// smem stage: SH 0, SL 8704, TH 17408, TL 26112 (32 rows x 272B); stage size 34816
#define CST 34816
__global__ void __launch_bounds__(256) mcov_mma(
    const __nv_bfloat16* __restrict__ snh, const __nv_bfloat16* __restrict__ snl,
    const __nv_bfloat16* __restrict__ tnh, const __nv_bfloat16* __restrict__ tnl,
    float* __restrict__ M)
{
    extern __shared__ char smem[];
    uint32_t sb = smem_to_u32(smem);
    const int tid = threadIdx.x, lane = tid & 31, wid = tid >> 5;
    const int wm = wid >> 2, wn = wid & 3;
    const int lr = lane >> 2, lc = lane & 3;
    const int b = blockIdx.y, split = blockIdx.x;

    const int r = tid >> 3, q = tid & 7;
    const size_t srow0 = (size_t)b * SS + split * 256;
    const size_t gIdx = (srow0 + r) * 128 + q * 16;
    const __nv_bfloat16 *pSh = snh + gIdx, *pSl = snl + gIdx;
    const __nv_bfloat16 *pTh = tnh + gIdx, *pTl = tnl + gIdx;
    const uint32_t dBase = sb + r * 272 + q * 32;

    float acc[4][4][4];
    #pragma unroll
    for (int i = 0; i < 4; i++)
        #pragma unroll
        for (int j = 0; j < 4; j++)
            #pragma unroll
            for (int k = 0; k < 4; k++) acc[i][j][k] = 0.f;

    {
        uint32_t d = dBase;
        CP16(d, pSh); CP16(d + 16, pSh + 8);
        CP16(d + 8704, pSl); CP16(d + 8704 + 16, pSl + 8);
        CP16(d + 17408, pTh); CP16(d + 17408 + 16, pTh + 8);
        CP16(d + 26112, pTl); CP16(d + 26112 + 16, pTl + 8);
        CP_COMMIT();
    }

    for (int c = 0; c < 8; c++) {
        if (c + 1 < 8) {
            uint32_t d = dBase + ((c + 1) & 1) * CST;
            const size_t co = (size_t)(c + 1) * 32 * 128;
            CP16(d, pSh + co); CP16(d + 16, pSh + co + 8);
            CP16(d + 8704, pSl + co); CP16(d + 8704 + 16, pSl + co + 8);
            CP16(d + 17408, pTh + co); CP16(d + 17408 + 16, pTh + co + 8);
            CP16(d + 26112, pTl + co); CP16(d + 26112 + 16, pTl + co + 8);
            CP_COMMIT();
            CP_WAIT(1);
        } else {
            CP_WAIT(0);
        }
        __syncthreads();
        uint32_t base = sb + (c & 1) * CST;
        #pragma unroll
        for (int ks = 0; ks < 2; ks++) {
            uint32_t ah[4][4], al[4][4], bh[4][2], bl[4][2];
            #pragma unroll
            for (int mt = 0; mt < 4; mt++) {
                int rowk = ks * 16 + (lane & 7) + ((lane >> 4) & 1) * 8;
                int colm = wm * 64 + mt * 16 + ((lane >> 3) & 1) * 8;
                uint32_t addr = base + (uint32_t)(rowk * 272 + colm * 2);
                LDSM4T(ah[mt][0], ah[mt][1], ah[mt][2], ah[mt][3], addr);
                LDSM4T(al[mt][0], al[mt][1], al[mt][2], al[mt][3], addr + 8704);
            }
            #pragma unroll
            for (int nt = 0; nt < 4; nt++) {
                int rowk = ks * 16 + (lane & 15);
                int coln = wn * 32 + nt * 8;
                uint32_t addr = base + 17408 + (uint32_t)(rowk * 272 + coln * 2);
                LDSM2T(bh[nt][0], bh[nt][1], addr);
                LDSM2T(bl[nt][0], bl[nt][1], addr + 8704);
            }
            #pragma unroll
            for (int mt = 0; mt < 4; mt++)
                #pragma unroll
                for (int nt = 0; nt < 4; nt++) {
                    MMA_BF16(acc[mt][nt], ah[mt], bh[nt]);
                    MMA_BF16(acc[mt][nt], ah[mt], bl[nt]);
                    MMA_BF16(acc[mt][nt], al[mt], bh[nt]);
                }
        }
        __syncthreads();
    }

    float* Mb = M + (size_t)b * 16384;
    #pragma unroll
    for (int mt = 0; mt < 4; mt++) {
        int row = wm * 64 + mt * 16 + lr;
        #pragma unroll
        for (int nt = 0; nt < 4; nt++) {
            int col = wn * 32 + nt * 8 + 2 * lc;
            atomicAdd(&Mb[(size_t)row * 128 + col], acc[mt][nt][0]);
            atomicAdd(&Mb[(size_t)row * 128 + col + 1], acc[mt][nt][1]);
            atomicAdd(&Mb[(size_t)(row + 8) * 128 + col], acc[mt][nt][2]);
            atomicAdd(&Mb[(size_t)(row + 8) * 128 + col + 1], acc[mt][nt][3]);
        }
    }
}

// ---------------- local windowed causal attention (writes hi/lo bf16) ----------------
__global__ __launch_bounds__(64) void lw_attn_k(const float* __restrict__ qkv,
                                                __nv_bfloat16* __restrict__ Ch,
                                                __nv_bfloat16* __restrict__ Cl)
{
    int g = blockIdx.x, h = blockIdx.y, i = threadIdx.x;
    __shared__ float ks[64][17];
    __shared__ float vs[64][17];
    size_t tbase = (size_t)g * 64;
    const float* kp = qkv + (tbase + i) * 384 + 128 + h * 16;
    const float* vp = kp + 128;
    #pragma unroll
    for (int d = 0; d < 16; d++) { ks[i][d] = kp[d]; vs[i][d] = vp[d]; }
    float q[16];
    const float* qp = qkv + (tbase + i) * 384 + h * 16;
    #pragma unroll
    for (int d = 0; d < 16; d++) q[d] = qp[d];
    __syncthreads();
    float sc[64];
    float mx = -1e30f;
    #pragma unroll
    for (int j = 0; j < 64; j++) {
        float dv = 0.f;
        #pragma unroll
        for (int d = 0; d < 16; d++) dv += q[d] * ks[j][d];
        sc[j] = (j <= i) ? dv * 0.25f : -INFINITY;
        mx = fmaxf(mx, sc[j]);
    }
    float sum = 0.f;
    #pragma unroll
    for (int j = 0; j < 64; j++) { float e = expf(sc[j] - mx); sc[j] = e; sum += e; }
    float o[16] = {};
    #pragma unroll
    for (int j = 0; j < 64; j++) {
        float w = sc[j];
        #pragma unroll
        for (int d = 0; d < 16; d++) o[d] += w * vs[j][d];
    }
    float inv = 1.f / sum;
    size_t ob = (tbase + i) * 128 + h * 16;
    #pragma unroll
    for (int d = 0; d < 16; d += 2)
        store_hl(Ch, Cl, ob + d, o[d] * inv, o[d + 1] * inv);
}

// ---------------- interaction MHA (len = B = 8), writes hi/lo bf16 ----------------
__global__ __launch_bounds__(64) void int_attn_k(const float* __restrict__ qkv,
                                                 __nv_bfloat16* __restrict__ Ch,
                                                 __nv_bfloat16* __restrict__ Cl)
{
    int s = blockIdx.x, tid = threadIdx.x;
    __shared__ float kvs[8][256];
    for (int idx = tid; idx < 8 * 256; idx += 64) {
        int jb = idx >> 8, c = idx & 255;
        kvs[jb][c] = qkv[((size_t)jb * SS + s) * 384 + 128 + c];
    }
    __syncthreads();
    int h = tid >> 3, qb = tid & 7;
    float q[16];
    const float* qp = qkv + ((size_t)qb * SS + s) * 384 + h * 16;
    #pragma unroll
    for (int d = 0; d < 16; d++) q[d] = qp[d];
    float sc[8];
    float mx = -1e30f;
    #pragma unroll
    for (int jb = 0; jb < 8; jb++) {
        float dv = 0.f;
        #pragma unroll
        for (int d = 0; d < 16; d++) dv += q[d] * kvs[jb][h * 16 + d];
        sc[jb] = dv * 0.25f;
        mx = fmaxf(mx, sc[jb]);
    }
    float sum = 0.f;
    #pragma unroll
    for (int jb = 0; jb < 8; jb++) { float e = expf(sc[jb] - mx); sc[jb] = e; sum += e; }
    float o[16] = {};
    #pragma unroll
    for (int jb = 0; jb < 8; jb++) {
        float w = sc[jb];
        #pragma unroll
        for (int d = 0; d < 16; d++) o[d] += w * kvs[jb][128 + h * 16 + d];
    }
    float inv = 1.f / sum;
    size_t ob = ((size_t)qb * SS + s) * 128 + h * 16;
    #pragma unroll
    for (int d = 0; d < 16; d += 2)
        store_hl(Ch, Cl, ob + d, o[d] * inv, o[d + 1] * inv);
}

extern "C" void kernel_launch(void* const* d_in, const int* in_sizes, int n_in,
                              void* d_out, int out_size)
{
    const float* x        = (const float*)d_in[0];
    const float* sp       = (const float*)d_in[1];
    const float* tp       = (const float*)d_in[2];
    const float* lw_in_b  = (const float*)d_in[4];
    const float* lw_out_b = (const float*)d_in[6];
    const float* spat_b   = (const float*)d_in[8];
    const float* temp_b   = (const float*)d_in[10];
    const float* int_in_b = (const float*)d_in[12];
    const float* int_out_b= (const float*)d_in[14];
    const float* ffn_b1   = (const float*)d_in[16];
    const float* ffn_b2   = (const float*)d_in[18];
    const float* ln1_g    = (const float*)d_in[19];
    const float* ln1_b    = (const float*)d_in[20];
    const float* ln2_g    = (const float*)d_in[21];
    const float* ln2_b    = (const float*)d_in[22];
    float* out = (float*)d_out;

    float* f32 = nullptr;
    __nv_bfloat16* bf = nullptr;
    cudaGetSymbolAddress((void**)&f32, g_f32);
    cudaGetSymbolAddress((void**)&bf, g_bf);

    static bool attr_done = false;
    if (!attr_done) {
        cudaFuncSetAttribute(gemm_mma, cudaFuncAttributeMaxDynamicSharedMemorySize, 2 * GST);
        cudaFuncSetAttribute(mcov_mma, cudaFuncAttributeMaxDynamicSharedMemorySize, 2 * CST);
        attr_done = true;
    }

    float* qkv  = f32 + F_QKV;
    float* bufb = f32 + F_BUFB;
    float* bufc = f32 + F_BUFC;
    float* snf  = f32 + F_SNF;
    float* bM   = f32 + F_M;
    float* bsim = f32 + F_SIM;

    #define BH(o) (bf + (o))
    #define BL(o, n) (bf + (o) + (n))
    const unsigned NT = 2097152;

    // 1. convert x, sp, tp + all weights into hi/lo bf16
    CvtSrc cs;
    cs.p[0] = x; cs.p[1] = sp; cs.p[2] = tp;
    cs.p[3] = (const float*)d_in[3];   // lw_in_w
    cs.p[4] = (const float*)d_in[5];   // lw_out_w
    cs.p[5] = (const float*)d_in[7];   // spat_w
    cs.p[6] = (const float*)d_in[9];   // temp_w
    cs.p[7] = (const float*)d_in[11];  // int_in_w
    cs.p[8] = (const float*)d_in[13];  // int_out_w
    cs.p[9] = (const float*)d_in[15];  // ffn_w1
    cs.p[10] = (const float*)d_in[17]; // ffn_w2
    cvt_all_k<<<592, 256>>>(cs);

    // 2. qkv projection (fp32 out for attention)
    gemm_mma<<<dim3(3, 128), 256, 2 * GST>>>(
        BH(H_X), BL(H_X, NT), nullptr, nullptr, BH(H_LWIN), BL(H_LWIN, 49152),
        lw_in_b, qkv, nullptr, nullptr, nullptr, nullptr, nullptr, nullptr,
        nullptr, nullptr, 128, 384, EP_F32, 0);
    // 3. windowed causal attention
    lw_attn_k<<<dim3(256, 8), 64>>>(qkv, BH(H_ATT), BL(H_ATT, NT));
    // 4. out-proj + residual(x) + LN1 -> bufb fp32 + hl
    gemm_mma<<<dim3(1, 128), 256, 2 * GST>>>(
        BH(H_ATT), BL(H_ATT, NT), nullptr, nullptr, BH(H_LWOUT), BL(H_LWOUT, 16384),
        lw_out_b, bufb, BH(H_BUFB), BL(H_BUFB, NT), nullptr, nullptr,
        x, nullptr, ln1_g, ln1_b, 128, 128, EP_LN, 0);
    // 5. ffn1 + GELU -> bufh hl
    gemm_mma<<<dim3(4, 128), 256, 2 * GST>>>(
        BH(H_BUFB), BL(H_BUFB, NT), nullptr, nullptr, BH(H_FW1), BL(H_FW1, 65536),
        ffn_b1, nullptr, BH(H_BUFH), BL(H_BUFH, 8388608), nullptr, nullptr,
        nullptr, nullptr, nullptr, nullptr, 128, 512, EP_GELU, 0);
    // 6. ffn2 + residual(bufb) + LN2 -> bufc fp32
    gemm_mma<<<dim3(1, 128), 256, 2 * GST>>>(
        BH(H_BUFH), BL(H_BUFH, 8388608), nullptr, nullptr, BH(H_FW2), BL(H_FW2, 65536),
        ffn_b2, bufc, nullptr, nullptr, nullptr, nullptr,
        bufb, nullptr, ln2_g, ln2_b, 512, 128, EP_LN2, 0);
    // 7. spatial embed + cosnorm -> se hl (raw), sn fp32 + hl
    gemm_mma<<<dim3(1, 128), 256, 2 * GST>>>(
        BH(H_SP), BL(H_SP, NT), nullptr, nullptr, BH(H_SPATW), BL(H_SPATW, 16384),
        spat_b, snf, BH(H_SE), BL(H_SE, NT), BH(H_SN), BL(H_SN, NT),
        nullptr, nullptr, nullptr, nullptr, 128, 128, EP_COS, 0);
    // 8. temporal embed + cosnorm -> te hl (raw), tn hl
    gemm_mma<<<dim3(1, 128), 256, 2 * GST>>>(
        BH(H_TP), BL(H_TP, NT), nullptr, nullptr, BH(H_TEMPW), BL(H_TEMPW, 16384),
        temp_b, nullptr, BH(H_TE), BL(H_TE, NT), BH(H_TN), BL(H_TN, NT),
        nullptr, nullptr, nullptr, nullptr, 128, 128, EP_COS, 0);
    // 9-11. M covariance + convert
    zero_k<<<512, 256>>>(bM, 8 * 128 * 128);
    mcov_mma<<<dim3(8, 8), 256, 2 * CST>>>(
        BH(H_SN), BL(H_SN, NT), BH(H_TN), BL(H_TN, NT), bM);
    cvtm_k<<<128, 256>>>(bM, BH(H_M), BL(H_M, 131072), 131072);
    // 12. sim = (1/S) sn . (M tn)
    gemm_mma<<<dim3(1, 128), 256, 2 * GST>>>(
        BH(H_TN), BL(H_TN, NT), nullptr, nullptr, BH(H_M), BL(H_M, 131072),
        nullptr, bsim, nullptr, nullptr, nullptr, nullptr,
        snf, nullptr, nullptr, nullptr, 128, 0, EP_SIMDOT, 16384);
    // 13. interaction qkv (q from se, k/v from te) in one launch
    gemm_mma<<<dim3(3, 128), 256, 2 * GST>>>(
        BH(H_SE), BL(H_SE, NT), BH(H_TE), BL(H_TE, NT), BH(H_INTIN), BL(H_INTIN, 49152),
        int_in_b, qkv, nullptr, nullptr, nullptr, nullptr, nullptr, nullptr,
        nullptr, nullptr, 128, 384, EP_F32, 0);
    // 14. interaction attention
    int_attn_k<<<SS, 64>>>(qkv, BH(H_ATT), BL(H_ATT, NT));
    // 15. final: out = bufc + sim[t] * (attn @ Wout^T + bout)
    gemm_mma<<<dim3(1, 128), 256, 2 * GST>>>(
        BH(H_ATT), BL(H_ATT, NT), nullptr, nullptr, BH(H_INTOUT), BL(H_INTOUT, 16384),
        int_out_b, out, nullptr, nullptr, nullptr, nullptr,
        bufc, bsim, nullptr, nullptr, 128, 128, EP_FINAL, 0);
}

// round 5
// speedup vs baseline: 2.1266x; 1.0034x over previous
#include <cuda_runtime.h>
#include <cuda_bf16.h>
#include <cstdint>
#include <math.h>

#define BB 8
#define SS 2048
#define TT 16384

// ---------------- float scratch ----------------
#define F_QKV  0u          // 16384*384
#define F_BUFB 6291456u    // 16384*128
#define F_BUFC 8388608u
#define F_SNF  10485760u
#define F_M    12582912u   // 8*128*128
#define F_SIM  12713984u   // 16384
#define F_TOT  12730368u
__device__ float g_f32[F_TOT];

// ---------------- bf16 scratch (each tensor: HI then LO contiguous) ----------------
#define H_X      0u
#define H_SP     4194304u
#define H_TP     8388608u
#define H_ATT    12582912u
#define H_BUFB   16777216u
#define H_BUFH   20971520u   // 16384*512 *2
#define H_SE     37748736u
#define H_SN     41943040u
#define H_TE     46137344u
#define H_TN     50331648u
#define H_M      54525952u   // 131072*2
#define H_LWIN   54788096u   // 49152*2
#define H_LWOUT  54886400u   // 16384*2
#define H_SPATW  54919168u
#define H_TEMPW  54951936u
#define H_INTIN  54984704u   // 49152*2
#define H_INTOUT 55083008u
#define H_FW1    55115776u   // 65536*2
#define H_FW2    55246848u
#define BF_TOT   55377920u
__device__ __nv_bfloat16 g_bf[BF_TOT];

enum { EP_F32 = 0, EP_LN = 1, EP_GELU = 2, EP_LN2 = 3, EP_COS = 4, EP_FINAL = 5, EP_SIMDOT = 6 };

__device__ __forceinline__ uint32_t smem_to_u32(const void* p) {
    uint32_t a;
    asm("{ .reg .u64 t; cvta.to.shared.u64 t, %1; cvt.u32.u64 %0, t; }" : "=r"(a) : "l"(p));
    return a;
}

#define CP16(dst, src) do { \
    unsigned long long _gs = (unsigned long long)__cvta_generic_to_global((const void*)(src)); \
    asm volatile("cp.async.cg.shared.global [%0], [%1], 16;" :: "r"(dst), "l"(_gs)); } while (0)
#define CP_COMMIT() asm volatile("cp.async.commit_group;" ::: "memory")
#define CP_WAIT(n) asm volatile("cp.async.wait_group %0;" :: "n"(n) : "memory")

#define LDSM4(r0, r1, r2, r3, addr) \
    asm volatile("ldmatrix.sync.aligned.m8n8.x4.shared.b16 {%0,%1,%2,%3}, [%4];" \
        : "=r"(r0), "=r"(r1), "=r"(r2), "=r"(r3) : "r"(addr))
#define LDSM4T(r0, r1, r2, r3, addr) \
    asm volatile("ldmatrix.sync.aligned.m8n8.x4.trans.shared.b16 {%0,%1,%2,%3}, [%4];" \
        : "=r"(r0), "=r"(r1), "=r"(r2), "=r"(r3) : "r"(addr))
#define LDSM2T(r0, r1, addr) \
    asm volatile("ldmatrix.sync.aligned.m8n8.x2.trans.shared.b16 {%0,%1}, [%2];" \
        : "=r"(r0), "=r"(r1) : "r"(addr))

#define MMA_BF16(c, a, b) \
    asm volatile("mma.sync.aligned.m16n8k16.row.col.f32.bf16.bf16.f32 " \
        "{%0,%1,%2,%3}, {%4,%5,%6,%7}, {%8,%9}, {%0,%1,%2,%3};" \
        : "+f"((c)[0]), "+f"((c)[1]), "+f"((c)[2]), "+f"((c)[3]) \
        : "r"((a)[0]), "r"((a)[1]), "r"((a)[2]), "r"((a)[3]), "r"((b)[0]), "r"((b)[1]))

__device__ __forceinline__ void cvt_split4(float4 v, uint2& hv, uint2& lv) {
    __nv_bfloat16 h0 = __float2bfloat16_rn(v.x);
    __nv_bfloat16 h1 = __float2bfloat16_rn(v.y);
    __nv_bfloat16 h2 = __float2bfloat16_rn(v.z);
    __nv_bfloat16 h3 = __float2bfloat16_rn(v.w);
    __nv_bfloat16 l0 = __float2bfloat16_rn(v.x - __bfloat162float(h0));
    __nv_bfloat16 l1 = __float2bfloat16_rn(v.y - __bfloat162float(h1));
    __nv_bfloat16 l2 = __float2bfloat16_rn(v.z - __bfloat162float(h2));
    __nv_bfloat16 l3 = __float2bfloat16_rn(v.w - __bfloat162float(h3));
    hv.x = (uint32_t)__bfloat16_as_ushort(h0) | ((uint32_t)__bfloat16_as_ushort(h1) << 16);
    hv.y = (uint32_t)__bfloat16_as_ushort(h2) | ((uint32_t)__bfloat16_as_ushort(h3) << 16);
    lv.x = (uint32_t)__bfloat16_as_ushort(l0) | ((uint32_t)__bfloat16_as_ushort(l1) << 16);
    lv.y = (uint32_t)__bfloat16_as_ushort(l2) | ((uint32_t)__bfloat16_as_ushort(l3) << 16);
}

__device__ __forceinline__ void store_hl(__nv_bfloat16* Ch, __nv_bfloat16* Cl,
                                         size_t idx, float w0, float w1) {
    __nv_bfloat16 h0 = __float2bfloat16_rn(w0), h1 = __float2bfloat16_rn(w1);
    __nv_bfloat162 hp; hp.x = h0; hp.y = h1;
    *(__nv_bfloat162*)(Ch + idx) = hp;
    __nv_bfloat162 lp;
    lp.x = __float2bfloat16_rn(w0 - __bfloat162float(h0));
    lp.y = __float2bfloat16_rn(w1 - __bfloat162float(h1));
    *(__nv_bfloat162*)(Cl + idx) = lp;
}

__device__ __forceinline__ float gelu_f(float v) {
    return 0.5f * v * (1.0f + erff(v * 0.70710678118654752f));
}

// ============== pre-split conversion of inputs/weights ==============
struct CvtSrc { const float* p[11]; };
__global__ void __launch_bounds__(256) cvt_all_k(CvtSrc s)
{
    const int ns[11] = {2097152, 2097152, 2097152, 49152, 16384, 16384, 16384,
                        49152, 16384, 65536, 65536};
    const unsigned offs[11] = {H_X, H_SP, H_TP, H_LWIN, H_LWOUT, H_SPATW, H_TEMPW,
                               H_INTIN, H_INTOUT, H_FW1, H_FW2};
    int stride = gridDim.x * blockDim.x;
    int t = blockIdx.x * blockDim.x + threadIdx.x;
    for (int seg = 0; seg < 11; seg++) {
        const float4* src = (const float4*)s.p[seg];
        __nv_bfloat16* dh = g_bf + offs[seg];
        __nv_bfloat16* dl = dh + ns[seg];
        int m = ns[seg] >> 2;
        for (int i = t; i < m; i += stride) {
            uint2 hv, lv;
            cvt_split4(src[i], hv, lv);
            *(uint2*)(dh + (size_t)i * 4) = hv;
            *(uint2*)(dl + (size_t)i * 4) = lv;
        }
    }
}

__global__ void __launch_bounds__(256) cvtm_k(const float* __restrict__ src,
                                              __nv_bfloat16* dh, __nv_bfloat16* dl, int n)
{
    int t = blockIdx.x * blockDim.x + threadIdx.x;
    int m = n >> 2;
    for (int i = t; i < m; i += gridDim.x * blockDim.x) {
        uint2 hv, lv;
        cvt_split4(((const float4*)src)[i], hv, lv);
        *(uint2*)(dh + (size_t)i * 4) = hv;
        *(uint2*)(dl + (size_t)i * 4) = lv;
    }
}

__global__ void zero_k(float* p, int n)
{
    int i = blockIdx.x * 256 + threadIdx.x;
    if (i < n) p[i] = 0.f;
}

// ============== generic bf16-split GEMM: C[M,N] = A @ W^T ==============
// Tile 64(M) x 128(N), 128 threads = 4 warps (2 wm x 2 wn), warp tile 32x64.
// smem stage (30720B): AH +0 (64x80), AL +5120, BH +10240 (128x80), BL +20480.
#define GST 30720
__global__ void __launch_bounds__(128, 3) gemm_mma(
    const __nv_bfloat16* __restrict__ Ah, const __nv_bfloat16* __restrict__ Al,
    const __nv_bfloat16* __restrict__ A2h, const __nv_bfloat16* __restrict__ A2l,
    const __nv_bfloat16* __restrict__ Wh, const __nv_bfloat16* __restrict__ Wl,
    const float* __restrict__ bias, float* __restrict__ C,
    __nv_bfloat16* __restrict__ Ch, __nv_bfloat16* __restrict__ Cl,
    __nv_bfloat16* __restrict__ C2h, __nv_bfloat16* __restrict__ C2l,
    const float* __restrict__ R, const float* __restrict__ rs,
    const float* __restrict__ gam, const float* __restrict__ bet,
    int K, int ldc, int mode, int batchW)
{
    extern __shared__ char smem[];
    uint32_t sb = smem_to_u32(smem);
    const int tid = threadIdx.x, lane = tid & 31, wid = tid >> 5;
    const int wm = wid >> 1, wn = wid & 1;
    const int lr = lane >> 2, lc = lane & 3;
    const int bm = blockIdx.y * 64, bn = blockIdx.x * 128;

    const __nv_bfloat16* Auh = (A2h && bn > 0) ? A2h : Ah;
    const __nv_bfloat16* Aul = (A2h && bn > 0) ? A2l : Al;
    if (batchW) { Wh += (size_t)(bm >> 11) * (size_t)batchW; Wl += (size_t)(bm >> 11) * (size_t)batchW; }

    const int ra = tid >> 1, half = tid & 1;
    const size_t aIdx = (size_t)(bm + ra) * K + half * 16;
    const size_t wIdx = (size_t)(bn + tid) * K;
    const __nv_bfloat16 *pAh = Auh + aIdx, *pAl = Aul + aIdx;
    const __nv_bfloat16 *pWh = Wh + wIdx, *pWl = Wl + wIdx;
    const uint32_t dA = sb + ra * 80 + half * 32;
    const uint32_t dB = sb + 10240 + tid * 80;

    float acc[2][8][4];
    #pragma unroll
    for (int i = 0; i < 2; i++)
        #pragma unroll
        for (int j = 0; j < 8; j++)
            #pragma unroll
            for (int k = 0; k < 4; k++) acc[i][j][k] = 0.f;

    const int nch = K >> 5;

    // prologue: chunk 0 into stage 0
    {
        CP16(dA, pAh); CP16(dA + 16, pAh + 8);
        CP16(dA + 5120, pAl); CP16(dA + 5120 + 16, pAl + 8);
        CP16(dB, pWh); CP16(dB + 16, pWh + 8);
        CP16(dB + 32, pWh + 16); CP16(dB + 48, pWh + 24);
        CP16(dB + 10240, pWl); CP16(dB + 10240 + 16, pWl + 8);
        CP16(dB + 10240 + 32, pWl + 16); CP16(dB + 10240 + 48, pWl + 24);
        CP_COMMIT();
    }

    for (int c = 0; c < nch; c++) {
        if (c + 1 < nch) {
            uint32_t stg = ((c + 1) & 1) * GST;
            const int co = (c + 1) * 32;
            CP16(dA + stg, pAh + co); CP16(dA + stg + 16, pAh + co + 8);
            CP16(dA + stg + 5120, pAl + co); CP16(dA + stg + 5120 + 16, pAl + co + 8);
            CP16(dB + stg, pWh + co); CP16(dB + stg + 16, pWh + co + 8);
            CP16(dB + stg + 32, pWh + co + 16); CP16(dB + stg + 48, pWh + co + 24);
            CP16(dB + stg + 10240, pWl + co); CP16(dB + stg + 10240 + 16, pWl + co + 8);
            CP16(dB + stg + 10240 + 32, pWl + co + 16); CP16(dB + stg + 10240 + 48, pWl + co + 24);
            CP_COMMIT();
            CP_WAIT(1);
        } else {
            CP_WAIT(0);
        }
        __syncthreads();
        uint32_t base = sb + (c & 1) * GST;
        #pragma unroll
        for (int ks = 0; ks < 2; ks++) {
            uint32_t ah[2][4], al[2][4], bh[8][2], bl[8][2];
            #pragma unroll
            for (int mt = 0; mt < 2; mt++) {
                uint32_t addr = base + (uint32_t)((wm * 32 + mt * 16 + (lane & 15)) * 80
                               + ks * 32 + ((lane >> 4) & 1) * 16);
                LDSM4(ah[mt][0], ah[mt][1], ah[mt][2], ah[mt][3], addr);
                LDSM4(al[mt][0], al[mt][1], al[mt][2], al[mt][3], addr + 5120);
            }
            #pragma unroll
            for (int ntp = 0; ntp < 4; ntp++) {
                int colrow = wn * 64 + ntp * 16 + ((lane >> 4) & 1) * 8 + (lane & 7);
                uint32_t addr = base + 10240 + (uint32_t)(colrow * 80
                               + ks * 32 + ((lane >> 3) & 1) * 16);
                LDSM4(bh[2 * ntp][0], bh[2 * ntp][1], bh[2 * ntp + 1][0], bh[2 * ntp + 1][1], addr);
                LDSM4(bl[2 * ntp][0], bl[2 * ntp][1], bl[2 * ntp + 1][0], bl[2 * ntp + 1][1], addr + 10240);
            }
            #pragma unroll
            for (int mt = 0; mt < 2; mt++)
                #pragma unroll
                for (int nt = 0; nt < 8; nt++) {
                    MMA_BF16(acc[mt][nt], ah[mt], bh[nt]);
                    MMA_BF16(acc[mt][nt], ah[mt], bl[nt]);
                    MMA_BF16(acc[mt][nt], al[mt], bh[nt]);
                }
        }
        __syncthreads();
    }

    // ---------------- epilogues ----------------
    if (mode == EP_SIMDOT) {
        float* simS = (float*)smem;
        if (tid < 64) simS[tid] = 0.f;
        __syncthreads();
        #pragma unroll
        for (int mt = 0; mt < 2; mt++) {
            int row0 = bm + wm * 32 + mt * 16 + lr;
            float d0 = 0.f, d1 = 0.f;
            #pragma unroll
            for (int nt = 0; nt < 8; nt++) {
                int col = bn + wn * 64 + nt * 8 + 2 * lc;
                float2 s0 = *(const float2*)(R + (size_t)row0 * 128 + col);
                float2 s1 = *(const float2*)(R + (size_t)(row0 + 8) * 128 + col);
                d0 += acc[mt][nt][0] * s0.x + acc[mt][nt][1] * s0.y;
                d1 += acc[mt][nt][2] * s1.x + acc[mt][nt][3] * s1.y;
            }
            d0 += __shfl_xor_sync(0xffffffffu, d0, 1);
            d0 += __shfl_xor_sync(0xffffffffu, d0, 2);
            d1 += __shfl_xor_sync(0xffffffffu, d1, 1);
            d1 += __shfl_xor_sync(0xffffffffu, d1, 2);
            if (lc == 0) {
                atomicAdd(&simS[wm * 32 + mt * 16 + lr], d0);
                atomicAdd(&simS[wm * 32 + mt * 16 + lr + 8], d1);
            }
        }
        __syncthreads();
        if (tid < 64) C[bm + tid] = simS[tid] * (1.f / 2048.f);
        return;
    }

    // bias + per-mode pre-transform (in place in acc)
    #pragma unroll
    for (int mt = 0; mt < 2; mt++) {
        int row = bm + wm * 32 + mt * 16 + lr;
        #pragma unroll
        for (int nt = 0; nt < 8; nt++) {
            int col = bn + wn * 64 + nt * 8 + 2 * lc;
            float2 b2 = *(const float2*)(bias + col);
            float* a = acc[mt][nt];
            a[0] += b2.x; a[1] += b2.y; a[2] += b2.x; a[3] += b2.y;
            if (mode == EP_LN || mode == EP_LN2) {
                float2 r0 = *(const float2*)(R + (size_t)row * ldc + col);
                float2 r1 = *(const float2*)(R + (size_t)(row + 8) * ldc + col);
                a[0] += r0.x; a[1] += r0.y; a[2] += r1.x; a[3] += r1.y;
            } else if (mode == EP_GELU) {
                a[0] = gelu_f(a[0]); a[1] = gelu_f(a[1]);
                a[2] = gelu_f(a[2]); a[3] = gelu_f(a[3]);
            } else if (mode == EP_FINAL) {
                float2 r0 = *(const float2*)(R + (size_t)row * ldc + col);
                float2 r1 = *(const float2*)(R + (size_t)(row + 8) * ldc + col);
                float sc0 = rs[row], sc1 = rs[row + 8];
                a[0] = r0.x + sc0 * a[0]; a[1] = r0.y + sc0 * a[1];
                a[2] = r1.x + sc1 * a[2]; a[3] = r1.y + sc1 * a[3];
            }
        }
    }

    if (mode == EP_LN || mode == EP_LN2 || mode == EP_COS) {
        float* ps = (float*)smem;        // [64][2]
        float* ps2 = ps + 128;
        #pragma unroll
        for (int mt = 0; mt < 2; mt++) {
            float p0 = 0.f, p1 = 0.f, q0 = 0.f, q1 = 0.f;
            #pragma unroll
            for (int nt = 0; nt < 8; nt++) {
                float* a = acc[mt][nt];
                p0 += a[0] + a[1]; q0 += a[0] * a[0] + a[1] * a[1];
                p1 += a[2] + a[3]; q1 += a[2] * a[2] + a[3] * a[3];
            }
            p0 += __shfl_xor_sync(0xffffffffu, p0, 1); p0 += __shfl_xor_sync(0xffffffffu, p0, 2);
            p1 += __shfl_xor_sync(0xffffffffu, p1, 1); p1 += __shfl_xor_sync(0xffffffffu, p1, 2);
            q0 += __shfl_xor_sync(0xffffffffu, q0, 1); q0 += __shfl_xor_sync(0xffffffffu, q0, 2);
            q1 += __shfl_xor_sync(0xffffffffu, q1, 1); q1 += __shfl_xor_sync(0xffffffffu, q1, 2);
            if (lc == 0) {
                int r0l = wm * 32 + mt * 16 + lr;
                ps[r0l * 2 + wn] = p0; ps2[r0l * 2 + wn] = q0;
                ps[(r0l + 8) * 2 + wn] = p1; ps2[(r0l + 8) * 2 + wn] = q1;
            }
        }
        __syncthreads();
        #pragma unroll
        for (int mt = 0; mt < 2; mt++) {
            int r0l = wm * 32 + mt * 16 + lr;
            float s0 = ps[r0l * 2] + ps[r0l * 2 + 1];
            float t0 = ps2[r0l * 2] + ps2[r0l * 2 + 1];
            float s1 = ps[(r0l + 8) * 2] + ps[(r0l + 8) * 2 + 1];
            float t1 = ps2[(r0l + 8) * 2] + ps2[(r0l + 8) * 2 + 1];
            int row0 = bm + r0l;
            if (mode == EP_COS) {
                float i0 = 1.f / fmaxf(sqrtf(t0), 1e-8f);
                float i1 = 1.f / fmaxf(sqrtf(t1), 1e-8f);
                #pragma unroll
                for (int nt = 0; nt < 8; nt++) {
                    int col = bn + wn * 64 + nt * 8 + 2 * lc;
                    float* a = acc[mt][nt];
                    size_t i0x = (size_t)row0 * ldc + col, i1x = (size_t)(row0 + 8) * ldc + col;
                    store_hl(Ch, Cl, i0x, a[0], a[1]);
                    store_hl(Ch, Cl, i1x, a[2], a[3]);
                    float n0 = a[0] * i0, n1 = a[1] * i0, n2 = a[2] * i1, n3 = a[3] * i1;
                    store_hl(C2h, C2l, i0x, n0, n1);
                    store_hl(C2h, C2l, i1x, n2, n3);
                    if (C) {
                        *(float2*)(C + i0x) = make_float2(n0, n1);
                        *(float2*)(C + i1x) = make_float2(n2, n3);
                    }
                }
            } else {
                float mu0 = s0 * (1.f / 128.f), mu1 = s1 * (1.f / 128.f);
                float rs0 = rsqrtf(t0 * (1.f / 128.f) - mu0 * mu0 + 1e-5f);
                float rs1 = rsqrtf(t1 * (1.f / 128.f) - mu1 * mu1 + 1e-5f);
                #pragma unroll
                for (int nt = 0; nt < 8; nt++) {
                    int col = bn + wn * 64 + nt * 8 + 2 * lc;
                    float* a = acc[mt][nt];
                    float2 g2 = *(const float2*)(gam + col);
                    float2 be2 = *(const float2*)(bet + col);
                    float w0 = (a[0] - mu0) * rs0 * g2.x + be2.x;
                    float w1 = (a[1] - mu0) * rs0 * g2.y + be2.y;
                    float w2 = (a[2] - mu1) * rs1 * g2.x + be2.x;
                    float w3 = (a[3] - mu1) * rs1 * g2.y + be2.y;
                    size_t i0x = (size_t)row0 * ldc + col, i1x = (size_t)(row0 + 8) * ldc + col;
                    *(float2*)(C + i0x) = make_float2(w0, w1);
                    *(float2*)(C + i1x) = make_float2(w2, w3);
                    if (Ch) {
                        store_hl(Ch, Cl, i0x, w0, w1);
                        store_hl(Ch, Cl, i1x, w2, w3);
                    }
                }
            }
        }
    } else {
        // EP_F32 / EP_FINAL / EP_GELU
        #pragma unroll
        for (int mt = 0; mt < 2; mt++) {
            int row = bm + wm * 32 + mt * 16 + lr;
            #pragma unroll
            for (int nt = 0; nt < 8; nt++) {
                int col = bn + wn * 64 + nt * 8 + 2 * lc;
                float* a = acc[mt][nt];
                size_t i0x = (size_t)row * ldc + col, i1x = (size_t)(row + 8) * ldc + col;
                if (mode == EP_GELU) {
                    store_hl(Ch, Cl, i0x, a[0], a[1]);
                    store_hl(Ch, Cl, i1x, a[2], a[3]);
                } else {
                    *(float2*)(C + i0x) = make_float2(a[0], a[1]);
                    *(float2*)(C + i1x) = make_float2(a[2], a[3]);
                }
            }
        }
    }
}

// ============== M covariance: M[b] += sn^T tn (contract over s) ==============
// smem stage: SH 0, SL 8704, TH 17408, TL 26112 (32 rows x 272B); stage size 34816
#define CST 34816
__global__ void __launch_bounds__(256) mcov_mma(
    const __nv_bfloat16* __restrict__ snh, const __nv_bfloat16* __restrict__ snl,
    const __nv_bfloat16* __restrict__ tnh, const __nv_bfloat16* __restrict__ tnl,
    float* __restrict__ M)
{
    extern __shared__ char smem[];
    uint32_t sb = smem_to_u32(smem);
    const int tid = threadIdx.x, lane = tid & 31, wid = tid >> 5;
    const int wm = wid >> 2, wn = wid & 3;
    const int lr = lane >> 2, lc = lane & 3;
    const int b = blockIdx.y, split = blockIdx.x;

    const int r = tid >> 3, q = tid & 7;
    const size_t srow0 = (size_t)b * SS + split * 128;
    const size_t gIdx = (srow0 + r) * 128 + q * 16;
    const __nv_bfloat16 *pSh = snh + gIdx, *pSl = snl + gIdx;
    const __nv_bfloat16 *pTh = tnh + gIdx, *pTl = tnl + gIdx;
    const uint32_t dBase = sb + r * 272 + q * 32;

    float acc[4][4][4];
    #pragma unroll
    for (int i = 0; i < 4; i++)
        #pragma unroll
        for (int j = 0; j < 4; j++)
            #pragma unroll
            for (int k = 0; k < 4; k++) acc[i][j][k] = 0.f;

    {
        uint32_t d = dBase;
        CP16(d, pSh); CP16(d + 16, pSh + 8);
        CP16(d + 8704, pSl); CP16(d + 8704 + 16, pSl + 8);
        CP16(d + 17408, pTh); CP16(d + 17408 + 16, pTh + 8);
        CP16(d + 26112, pTl); CP16(d + 26112 + 16, pTl + 8);
        CP_COMMIT();
    }

    for (int c = 0; c < 4; c++) {
        if (c + 1 < 4) {
            uint32_t d = dBase + ((c + 1) & 1) * CST;
            const size_t co = (size_t)(c + 1) * 32 * 128;
            CP16(d, pSh + co); CP16(d + 16, pSh + co + 8);
            CP16(d + 8704, pSl + co); CP16(d + 8704 + 16, pSl + co + 8);
            CP16(d + 17408, pTh + co); CP16(d + 17408 + 16, pTh + co + 8);
            CP16(d + 26112, pTl + co); CP16(d + 26112 + 16, pTl + co + 8);
            CP_COMMIT();
            CP_WAIT(1);
        } else {
            CP_WAIT(0);
        }
        __syncthreads();
        uint32_t base = sb + (c & 1) * CST;
        #pragma unroll
        for (int ks = 0; ks < 2; ks++) {
            uint32_t ah[4][4], al[4][4], bh[4][2], bl[4][2];
            #pragma unroll
            for (int mt = 0; mt < 4; mt++) {
                int rowk = ks * 16 + (lane & 7) + ((lane >> 4) & 1) * 8;
                int colm = wm * 64 + mt * 16 + ((lane >> 3) & 1) * 8;
                uint32_t addr = base + (uint32_t)(rowk * 272 + colm * 2);
                LDSM4T(ah[mt][0], ah[mt][1], ah[mt][2], ah[mt][3], addr);
                LDSM4T(al[mt][0], al[mt][1], al[mt][2], al[mt][3], addr + 8704);
            }
            #pragma unroll
            for (int nt = 0; nt < 4; nt++) {
                int rowk = ks * 16 + (lane & 15);
                int coln = wn * 32 + nt * 8;
                uint32_t addr = base + 17408 + (uint32_t)(rowk * 272 + coln * 2);
                LDSM2T(bh[nt][0], bh[nt][1], addr);
                LDSM2T(bl[nt][0], bl[nt][1], addr + 8704);
            }
            #pragma unroll
            for (int mt = 0; mt < 4; mt++)
                #pragma unroll
                for (int nt = 0; nt < 4; nt++) {
                    MMA_BF16(acc[mt][nt], ah[mt], bh[nt]);
                    MMA_BF16(acc[mt][nt], ah[mt], bl[nt]);
                    MMA_BF16(acc[mt][nt], al[mt], bh[nt]);
                }
        }
        __syncthreads();
    }

    float* Mb = M + (size_t)b * 16384;
    #pragma unroll
    for (int mt = 0; mt < 4; mt++) {
        int row = wm * 64 + mt * 16 + lr;
        #pragma unroll
        for (int nt = 0; nt < 4; nt++) {
            int col = wn * 32 + nt * 8 + 2 * lc;
            atomicAdd(&Mb[(size_t)row * 128 + col], acc[mt][nt][0]);
            atomicAdd(&Mb[(size_t)row * 128 + col + 1], acc[mt][nt][1]);
            atomicAdd(&Mb[(size_t)(row + 8) * 128 + col], acc[mt][nt][2]);
            atomicAdd(&Mb[(size_t)(row + 8) * 128 + col + 1], acc[mt][nt][3]);
        }
    }
}

// ---------------- local windowed causal attention (writes hi/lo bf16) ----------------
__global__ __launch_bounds__(64) void lw_attn_k(const float* __restrict__ qkv,
                                                __nv_bfloat16* __restrict__ Ch,
                                                __nv_bfloat16* __restrict__ Cl)
{
    int g = blockIdx.x, h = blockIdx.y, i = threadIdx.x;
    __shared__ float ks[64][17];
    __shared__ float vs[64][17];
    size_t tbase = (size_t)g * 64;
    const float* kp = qkv + (tbase + i) * 384 + 128 + h * 16;
    const float* vp = kp + 128;
    #pragma unroll
    for (int d = 0; d < 16; d++) { ks[i][d] = kp[d]; vs[i][d] = vp[d]; }
    float q[16];
    const float* qp = qkv + (tbase + i) * 384 + h * 16;
    #pragma unroll
    for (int d = 0; d < 16; d++) q[d] = qp[d];
    __syncthreads();
    float sc[64];
    float mx = -1e30f;
    #pragma unroll
    for (int j = 0; j < 64; j++) {
        float dv = 0.f;
        #pragma unroll
        for (int d = 0; d < 16; d++) dv += q[d] * ks[j][d];
        sc[j] = (j <= i) ? dv * 0.25f : -INFINITY;
        mx = fmaxf(mx, sc[j]);
    }
    float sum = 0.f;
    #pragma unroll
    for (int j = 0; j < 64; j++) { float e = expf(sc[j] - mx); sc[j] = e; sum += e; }
    float o[16] = {};
    #pragma unroll
    for (int j = 0; j < 64; j++) {
        float w = sc[j];
        #pragma unroll
        for (int d = 0; d < 16; d++) o[d] += w * vs[j][d];
    }
    float inv = 1.f / sum;
    size_t ob = (tbase + i) * 128 + h * 16;
    #pragma unroll
    for (int d = 0; d < 16; d += 2)
        store_hl(Ch, Cl, ob + d, o[d] * inv, o[d + 1] * inv);
}

// ---------------- interaction MHA (len = B = 8), writes hi/lo bf16 ----------------
__global__ __launch_bounds__(64) void int_attn_k(const float* __restrict__ qkv,
                                                 __nv_bfloat16* __restrict__ Ch,
                                                 __nv_bfloat16* __restrict__ Cl)
{
    int s = blockIdx.x, tid = threadIdx.x;
    __shared__ float kvs[8][256];
    for (int idx = tid; idx < 8 * 256; idx += 64) {
        int jb = idx >> 8, c = idx & 255;
        kvs[jb][c] = qkv[((size_t)jb * SS + s) * 384 + 128 + c];
    }
    __syncthreads();
    int h = tid >> 3, qb = tid & 7;
    float q[16];
    const float* qp = qkv + ((size_t)qb * SS + s) * 384 + h * 16;
    #pragma unroll
    for (int d = 0; d < 16; d++) q[d] = qp[d];
    float sc[8];
    float mx = -1e30f;
    #pragma unroll
    for (int jb = 0; jb < 8; jb++) {
        float dv = 0.f;
        #pragma unroll
        for (int d = 0; d < 16; d++) dv += q[d] * kvs[jb][h * 16 + d];
        sc[jb] = dv * 0.25f;
        mx = fmaxf(mx, sc[jb]);
    }
    float sum = 0.f;
    #pragma unroll
    for (int jb = 0; jb < 8; jb++) { float e = expf(sc[jb] - mx); sc[jb] = e; sum += e; }
    float o[16] = {};
    #pragma unroll
    for (int jb = 0; jb < 8; jb++) {
        float w = sc[jb];
        #pragma unroll
        for (int d = 0; d < 16; d++) o[d] += w * kvs[jb][128 + h * 16 + d];
    }
    float inv = 1.f / sum;
    size_t ob = ((size_t)qb * SS + s) * 128 + h * 16;
    #pragma unroll
    for (int d = 0; d < 16; d += 2)
        store_hl(Ch, Cl, ob + d, o[d] * inv, o[d + 1] * inv);
}

extern "C" void kernel_launch(void* const* d_in, const int* in_sizes, int n_in,
                              void* d_out, int out_size)
{
    const float* x        = (const float*)d_in[0];
    const float* sp       = (const float*)d_in[1];
    const float* tp       = (const float*)d_in[2];
    const float* lw_in_b  = (const float*)d_in[4];
    const float* lw_out_b = (const float*)d_in[6];
    const float* spat_b   = (const float*)d_in[8];
    const float* temp_b   = (const float*)d_in[10];
    const float* int_in_b = (const float*)d_in[12];
    const float* int_out_b= (const float*)d_in[14];
    const float* ffn_b1   = (const float*)d_in[16];
    const float* ffn_b2   = (const float*)d_in[18];
    const float* ln1_g    = (const float*)d_in[19];
    const float* ln1_b    = (const float*)d_in[20];
    const float* ln2_g    = (const float*)d_in[21];
    const float* ln2_b    = (const float*)d_in[22];
    float* out = (float*)d_out;

    float* f32 = nullptr;
    __nv_bfloat16* bf = nullptr;
    cudaGetSymbolAddress((void**)&f32, g_f32);
    cudaGetSymbolAddress((void**)&bf, g_bf);

    static bool attr_done = false;
    if (!attr_done) {
        cudaFuncSetAttribute(gemm_mma, cudaFuncAttributeMaxDynamicSharedMemorySize, 2 * GST);
        cudaFuncSetAttribute(mcov_mma, cudaFuncAttributeMaxDynamicSharedMemorySize, 2 * CST);
        attr_done = true;
    }

    float* qkv  = f32 + F_QKV;
    float* bufb = f32 + F_BUFB;
    float* bufc = f32 + F_BUFC;
    float* snf  = f32 + F_SNF;
    float* bM   = f32 + F_M;
    float* bsim = f32 + F_SIM;

    #define BH(o) (bf + (o))
    #define BL(o, n) (bf + (o) + (n))
    const unsigned NT = 2097152;

    // 1. convert x, sp, tp + all weights into hi/lo bf16
    CvtSrc cs;
    cs.p[0] = x; cs.p[1] = sp; cs.p[2] = tp;
    cs.p[3] = (const float*)d_in[3];   // lw_in_w
    cs.p[4] = (const float*)d_in[5];   // lw_out_w
    cs.p[5] = (const float*)d_in[7];   // spat_w
    cs.p[6] = (const float*)d_in[9];   // temp_w
    cs.p[7] = (const float*)d_in[11];  // int_in_w
    cs.p[8] = (const float*)d_in[13];  // int_out_w
    cs.p[9] = (const float*)d_in[15];  // ffn_w1
    cs.p[10] = (const float*)d_in[17]; // ffn_w2
    cvt_all_k<<<592, 256>>>(cs);

    // 2. qkv projection (fp32 out for attention)
    gemm_mma<<<dim3(3, 256), 128, 2 * GST>>>(
        BH(H_X), BL(H_X, NT), nullptr, nullptr, BH(H_LWIN), BL(H_LWIN, 49152),
        lw_in_b, qkv, nullptr, nullptr, nullptr, nullptr, nullptr, nullptr,
        nullptr, nullptr, 128, 384, EP_F32, 0);
    // 3. windowed causal attention
    lw_attn_k<<<dim3(256, 8), 64>>>(qkv, BH(H_ATT), BL(H_ATT, NT));
    // 4. out-proj + residual(x) + LN1 -> bufb fp32 + hl
    gemm_mma<<<dim3(1, 256), 128, 2 * GST>>>(
        BH(H_ATT), BL(H_ATT, NT), nullptr, nullptr, BH(H_LWOUT), BL(H_LWOUT, 16384),
        lw_out_b, bufb, BH(H_BUFB), BL(H_BUFB, NT), nullptr, nullptr,
        x, nullptr, ln1_g, ln1_b, 128, 128, EP_LN, 0);
    // 5. ffn1 + GELU -> bufh hl
    gemm_mma<<<dim3(4, 256), 128, 2 * GST>>>(
        BH(H_BUFB), BL(H_BUFB, NT), nullptr, nullptr, BH(H_FW1), BL(H_FW1, 65536),
        ffn_b1, nullptr, BH(H_BUFH), BL(H_BUFH, 8388608), nullptr, nullptr,
        nullptr, nullptr, nullptr, nullptr, 128, 512, EP_GELU, 0);
    // 6. ffn2 + residual(bufb) + LN2 -> bufc fp32
    gemm_mma<<<dim3(1, 256), 128, 2 * GST>>>(
        BH(H_BUFH), BL(H_BUFH, 8388608), nullptr, nullptr, BH(H_FW2), BL(H_FW2, 65536),
        ffn_b2, bufc, nullptr, nullptr, nullptr, nullptr,
        bufb, nullptr, ln2_g, ln2_b, 512, 128, EP_LN2, 0);
    // 7. spatial embed + cosnorm -> se hl (raw), sn fp32 + hl
    gemm_mma<<<dim3(1, 256), 128, 2 * GST>>>(
        BH(H_SP), BL(H_SP, NT), nullptr, nullptr, BH(H_SPATW), BL(H_SPATW, 16384),
        spat_b, snf, BH(H_SE), BL(H_SE, NT), BH(H_SN), BL(H_SN, NT),
        nullptr, nullptr, nullptr, nullptr, 128, 128, EP_COS, 0);
    // 8. temporal embed + cosnorm -> te hl (raw), tn hl
    gemm_mma<<<dim3(1, 256), 128, 2 * GST>>>(
        BH(H_TP), BL(H_TP, NT), nullptr, nullptr, BH(H_TEMPW), BL(H_TEMPW, 16384),
        temp_b, nullptr, BH(H_TE), BL(H_TE, NT), BH(H_TN), BL(H_TN, NT),
        nullptr, nullptr, nullptr, nullptr, 128, 128, EP_COS, 0);
    // 9-11. M covariance + convert
    zero_k<<<512, 256>>>(bM, 8 * 128 * 128);
    mcov_mma<<<dim3(16, 8), 256, 2 * CST>>>(
        BH(H_SN), BL(H_SN, NT), BH(H_TN), BL(H_TN, NT), bM);
    cvtm_k<<<128, 256>>>(bM, BH(H_M), BL(H_M, 131072), 131072);
    // 12. sim = (1/S) sn . (M tn)
    gemm_mma<<<dim3(1, 256), 128, 2 * GST>>>(
        BH(H_TN), BL(H_TN, NT), nullptr, nullptr, BH(H_M), BL(H_M, 131072),
        nullptr, bsim, nullptr, nullptr, nullptr, nullptr,
        snf, nullptr, nullptr, nullptr, 128, 0, EP_SIMDOT, 16384);
    // 13. interaction qkv (q from se, k/v from te) in one launch
    gemm_mma<<<dim3(3, 256), 128, 2 * GST>>>(
        BH(H_SE), BL(H_SE, NT), BH(H_TE), BL(H_TE, NT), BH(H_INTIN), BL(H_INTIN, 49152),
        int_in_b, qkv, nullptr, nullptr, nullptr, nullptr, nullptr, nullptr,
        nullptr, nullptr, 128, 384, EP_F32, 0);
    // 14. interaction attention
    int_attn_k<<<SS, 64>>>(qkv, BH(H_ATT), BL(H_ATT, NT));
    // 15. final: out = bufc + sim[t] * (attn @ Wout^T + bout)
    gemm_mma<<<dim3(1, 256), 128, 2 * GST>>>(
        BH(H_ATT), BL(H_ATT, NT), nullptr, nullptr, BH(H_INTOUT), BL(H_INTOUT, 16384),
        int_out_b, out, nullptr, nullptr, nullptr, nullptr,
        bufc, bsim, nullptr, nullptr, 128, 128, EP_FINAL, 0);
}

// round 6
// speedup vs baseline: 2.4695x; 1.1612x over previous
#include <cuda_runtime.h>
#include <cuda_bf16.h>
#include <cstdint>
#include <math.h>

#define BB 8
#define SS 2048
#define TT 16384

// ---------------- float scratch ----------------
#define F_QKV  0u          // 16384*384
#define F_BUFB 6291456u    // 16384*128
#define F_BUFC 8388608u
#define F_SNF  10485760u
#define F_M    12582912u   // 8*128*128
#define F_SIM  12713984u   // 16384
#define F_QKV2 12730368u   // 16384*384
#define F_TOT  19021824u
__device__ float g_f32[F_TOT];

// ---------------- bf16 scratch (each tensor: HI then LO contiguous) ----------------
#define H_X      0u
#define H_SP     4194304u
#define H_TP     8388608u
#define H_ATT    12582912u
#define H_BUFB   16777216u
#define H_BUFH   20971520u   // 16384*512 *2
#define H_SE     37748736u
#define H_SN     41943040u
#define H_TE     46137344u
#define H_TN     50331648u
#define H_M      54525952u   // 131072*2
#define H_LWIN   54788096u   // 49152*2
#define H_LWOUT  54886400u   // 16384*2
#define H_SPATW  54919168u
#define H_TEMPW  54951936u
#define H_INTIN  54984704u   // 49152*2
#define H_INTOUT 55083008u
#define H_FW1    55115776u   // 65536*2
#define H_FW2    55246848u
#define H_ATT2   55377920u   // 2097152*2
#define BF_TOT   59572224u
__device__ __nv_bfloat16 g_bf[BF_TOT];

enum { EP_F32 = 0, EP_LN = 1, EP_GELU = 2, EP_LN2 = 3, EP_COS = 4, EP_FINAL = 5, EP_SIMDOT = 6 };

__device__ __forceinline__ uint32_t smem_to_u32(const void* p) {
    uint32_t a;
    asm("{ .reg .u64 t; cvta.to.shared.u64 t, %1; cvt.u32.u64 %0, t; }" : "=r"(a) : "l"(p));
    return a;
}

#define CP16(dst, src) do { \
    unsigned long long _gs = (unsigned long long)__cvta_generic_to_global((const void*)(src)); \
    asm volatile("cp.async.cg.shared.global [%0], [%1], 16;" :: "r"(dst), "l"(_gs)); } while (0)
#define CP_COMMIT() asm volatile("cp.async.commit_group;" ::: "memory")
#define CP_WAIT(n) asm volatile("cp.async.wait_group %0;" :: "n"(n) : "memory")

#define LDSM4(r0, r1, r2, r3, addr) \
    asm volatile("ldmatrix.sync.aligned.m8n8.x4.shared.b16 {%0,%1,%2,%3}, [%4];" \
        : "=r"(r0), "=r"(r1), "=r"(r2), "=r"(r3) : "r"(addr))
#define LDSM4T(r0, r1, r2, r3, addr) \
    asm volatile("ldmatrix.sync.aligned.m8n8.x4.trans.shared.b16 {%0,%1,%2,%3}, [%4];" \
        : "=r"(r0), "=r"(r1), "=r"(r2), "=r"(r3) : "r"(addr))
#define LDSM2T(r0, r1, addr) \
    asm volatile("ldmatrix.sync.aligned.m8n8.x2.trans.shared.b16 {%0,%1}, [%2];" \
        : "=r"(r0), "=r"(r1) : "r"(addr))

#define MMA_BF16(c, a, b) \
    asm volatile("mma.sync.aligned.m16n8k16.row.col.f32.bf16.bf16.f32 " \
        "{%0,%1,%2,%3}, {%4,%5,%6,%7}, {%8,%9}, {%0,%1,%2,%3};" \
        : "+f"((c)[0]), "+f"((c)[1]), "+f"((c)[2]), "+f"((c)[3]) \
        : "r"((a)[0]), "r"((a)[1]), "r"((a)[2]), "r"((a)[3]), "r"((b)[0]), "r"((b)[1]))

__device__ __forceinline__ void cvt_split4(float4 v, uint2& hv, uint2& lv) {
    __nv_bfloat16 h0 = __float2bfloat16_rn(v.x);
    __nv_bfloat16 h1 = __float2bfloat16_rn(v.y);
    __nv_bfloat16 h2 = __float2bfloat16_rn(v.z);
    __nv_bfloat16 h3 = __float2bfloat16_rn(v.w);
    __nv_bfloat16 l0 = __float2bfloat16_rn(v.x - __bfloat162float(h0));
    __nv_bfloat16 l1 = __float2bfloat16_rn(v.y - __bfloat162float(h1));
    __nv_bfloat16 l2 = __float2bfloat16_rn(v.z - __bfloat162float(h2));
    __nv_bfloat16 l3 = __float2bfloat16_rn(v.w - __bfloat162float(h3));
    hv.x = (uint32_t)__bfloat16_as_ushort(h0) | ((uint32_t)__bfloat16_as_ushort(h1) << 16);
    hv.y = (uint32_t)__bfloat16_as_ushort(h2) | ((uint32_t)__bfloat16_as_ushort(h3) << 16);
    lv.x = (uint32_t)__bfloat16_as_ushort(l0) | ((uint32_t)__bfloat16_as_ushort(l1) << 16);
    lv.y = (uint32_t)__bfloat16_as_ushort(l2) | ((uint32_t)__bfloat16_as_ushort(l3) << 16);
}

__device__ __forceinline__ void store_hl(__nv_bfloat16* Ch, __nv_bfloat16* Cl,
                                         size_t idx, float w0, float w1) {
    __nv_bfloat16 h0 = __float2bfloat16_rn(w0), h1 = __float2bfloat16_rn(w1);
    __nv_bfloat162 hp; hp.x = h0; hp.y = h1;
    *(__nv_bfloat162*)(Ch + idx) = hp;
    __nv_bfloat162 lp;
    lp.x = __float2bfloat16_rn(w0 - __bfloat162float(h0));
    lp.y = __float2bfloat16_rn(w1 - __bfloat162float(h1));
    *(__nv_bfloat162*)(Cl + idx) = lp;
}

__device__ __forceinline__ float gelu_f(float v) {
    return 0.5f * v * (1.0f + erff(v * 0.70710678118654752f));
}

// ============== pre-split conversion ==============
struct CvtSrc { const float* p[6]; int n[6]; unsigned off[6]; int cnt; };
__global__ void __launch_bounds__(256) cvt_k(CvtSrc s)
{
    int stride = gridDim.x * blockDim.x;
    int t = blockIdx.x * blockDim.x + threadIdx.x;
    for (int seg = 0; seg < s.cnt; seg++) {
        const float4* src = (const float4*)s.p[seg];
        __nv_bfloat16* dh = g_bf + s.off[seg];
        __nv_bfloat16* dl = dh + s.n[seg];
        int m = s.n[seg] >> 2;
        for (int i = t; i < m; i += stride) {
            uint2 hv, lv;
            cvt_split4(src[i], hv, lv);
            *(uint2*)(dh + (size_t)i * 4) = hv;
            *(uint2*)(dl + (size_t)i * 4) = lv;
        }
    }
}

__global__ void __launch_bounds__(256) cvtm_k(const float* __restrict__ src,
                                              __nv_bfloat16* dh, __nv_bfloat16* dl, int n)
{
    int t = blockIdx.x * blockDim.x + threadIdx.x;
    int m = n >> 2;
    for (int i = t; i < m; i += gridDim.x * blockDim.x) {
        uint2 hv, lv;
        cvt_split4(((const float4*)src)[i], hv, lv);
        *(uint2*)(dh + (size_t)i * 4) = hv;
        *(uint2*)(dl + (size_t)i * 4) = lv;
    }
}

__global__ void zero_k(float* p, int n)
{
    int i = blockIdx.x * 256 + threadIdx.x;
    if (i < n) p[i] = 0.f;
}

// ============== generic bf16-split GEMM: C[M,N] = A @ W^T ==============
// Tile 64(M) x 128(N), 128 threads = 4 warps (2 wm x 2 wn), warp tile 32x64.
// smem stage (30720B): AH +0 (64x80), AL +5120, BH +10240 (128x80), BL +20480.
#define GST 30720
__global__ void __launch_bounds__(128, 3) gemm_mma(
    const __nv_bfloat16* __restrict__ Ah, const __nv_bfloat16* __restrict__ Al,
    const __nv_bfloat16* __restrict__ A2h, const __nv_bfloat16* __restrict__ A2l,
    const __nv_bfloat16* __restrict__ Wh, const __nv_bfloat16* __restrict__ Wl,
    const float* __restrict__ bias, float* __restrict__ C,
    __nv_bfloat16* __restrict__ Ch, __nv_bfloat16* __restrict__ Cl,
    __nv_bfloat16* __restrict__ C2h, __nv_bfloat16* __restrict__ C2l,
    const float* __restrict__ R, const float* __restrict__ rs,
    const float* __restrict__ gam, const float* __restrict__ bet,
    int K, int ldc, int mode, int batchW)
{
    extern __shared__ char smem[];
    uint32_t sb = smem_to_u32(smem);
    const int tid = threadIdx.x, lane = tid & 31, wid = tid >> 5;
    const int wm = wid >> 1, wn = wid & 1;
    const int lr = lane >> 2, lc = lane & 3;
    const int bm = blockIdx.y * 64, bn = blockIdx.x * 128;

    const __nv_bfloat16* Auh = (A2h && bn > 0) ? A2h : Ah;
    const __nv_bfloat16* Aul = (A2h && bn > 0) ? A2l : Al;
    if (batchW) { Wh += (size_t)(bm >> 11) * (size_t)batchW; Wl += (size_t)(bm >> 11) * (size_t)batchW; }

    const int ra = tid >> 1, half = tid & 1;
    const size_t aIdx = (size_t)(bm + ra) * K + half * 16;
    const size_t wIdx = (size_t)(bn + tid) * K;
    const __nv_bfloat16 *pAh = Auh + aIdx, *pAl = Aul + aIdx;
    const __nv_bfloat16 *pWh = Wh + wIdx, *pWl = Wl + wIdx;
    const uint32_t dA = sb + ra * 80 + half * 32;
    const uint32_t dB = sb + 10240 + tid * 80;

    float acc[2][8][4];
    #pragma unroll
    for (int i = 0; i < 2; i++)
        #pragma unroll
        for (int j = 0; j < 8; j++)
            #pragma unroll
            for (int k = 0; k < 4; k++) acc[i][j][k] = 0.f;

    const int nch = K >> 5;

    {
        CP16(dA, pAh); CP16(dA + 16, pAh + 8);
        CP16(dA + 5120, pAl); CP16(dA + 5120 + 16, pAl + 8);
        CP16(dB, pWh); CP16(dB + 16, pWh + 8);
        CP16(dB + 32, pWh + 16); CP16(dB + 48, pWh + 24);
        CP16(dB + 10240, pWl); CP16(dB + 10240 + 16, pWl + 8);
        CP16(dB + 10240 + 32, pWl + 16); CP16(dB + 10240 + 48, pWl + 24);
        CP_COMMIT();
    }

    for (int c = 0; c < nch; c++) {
        if (c + 1 < nch) {
            uint32_t stg = ((c + 1) & 1) * GST;
            const int co = (c + 1) * 32;
            CP16(dA + stg, pAh + co); CP16(dA + stg + 16, pAh + co + 8);
            CP16(dA + stg + 5120, pAl + co); CP16(dA + stg + 5120 + 16, pAl + co + 8);
            CP16(dB + stg, pWh + co); CP16(dB + stg + 16, pWh + co + 8);
            CP16(dB + stg + 32, pWh + co + 16); CP16(dB + stg + 48, pWh + co + 24);
            CP16(dB + stg + 10240, pWl + co); CP16(dB + stg + 10240 + 16, pWl + co + 8);
            CP16(dB + stg + 10240 + 32, pWl + co + 16); CP16(dB + stg + 10240 + 48, pWl + co + 24);
            CP_COMMIT();
            CP_WAIT(1);
        } else {
            CP_WAIT(0);
        }
        __syncthreads();
        uint32_t base = sb + (c & 1) * GST;
        #pragma unroll
        for (int ks = 0; ks < 2; ks++) {
            uint32_t ah[2][4], al[2][4], bh[8][2], bl[8][2];
            #pragma unroll
            for (int mt = 0; mt < 2; mt++) {
                uint32_t addr = base + (uint32_t)((wm * 32 + mt * 16 + (lane & 15)) * 80
                               + ks * 32 + ((lane >> 4) & 1) * 16);
                LDSM4(ah[mt][0], ah[mt][1], ah[mt][2], ah[mt][3], addr);
                LDSM4(al[mt][0], al[mt][1], al[mt][2], al[mt][3], addr + 5120);
            }
            #pragma unroll
            for (int ntp = 0; ntp < 4; ntp++) {
                int colrow = wn * 64 + ntp * 16 + ((lane >> 4) & 1) * 8 + (lane & 7);
                uint32_t addr = base + 10240 + (uint32_t)(colrow * 80
                               + ks * 32 + ((lane >> 3) & 1) * 16);
                LDSM4(bh[2 * ntp][0], bh[2 * ntp][1], bh[2 * ntp + 1][0], bh[2 * ntp + 1][1], addr);
                LDSM4(bl[2 * ntp][0], bl[2 * ntp][1], bl[2 * ntp + 1][0], bl[2 * ntp + 1][1], addr + 10240);
            }
            #pragma unroll
            for (int mt = 0; mt < 2; mt++)
                #pragma unroll
                for (int nt = 0; nt < 8; nt++) {
                    MMA_BF16(acc[mt][nt], ah[mt], bh[nt]);
                    MMA_BF16(acc[mt][nt], ah[mt], bl[nt]);
                    MMA_BF16(acc[mt][nt], al[mt], bh[nt]);
                }
        }
        __syncthreads();
    }

    // ---------------- epilogues ----------------
    if (mode == EP_SIMDOT) {
        float* simS = (float*)smem;
        if (tid < 64) simS[tid] = 0.f;
        __syncthreads();
        #pragma unroll
        for (int mt = 0; mt < 2; mt++) {
            int row0 = bm + wm * 32 + mt * 16 + lr;
            float d0 = 0.f, d1 = 0.f;
            #pragma unroll
            for (int nt = 0; nt < 8; nt++) {
                int col = bn + wn * 64 + nt * 8 + 2 * lc;
                float2 s0 = *(const float2*)(R + (size_t)row0 * 128 + col);
                float2 s1 = *(const float2*)(R + (size_t)(row0 + 8) * 128 + col);
                d0 += acc[mt][nt][0] * s0.x + acc[mt][nt][1] * s0.y;
                d1 += acc[mt][nt][2] * s1.x + acc[mt][nt][3] * s1.y;
            }
            d0 += __shfl_xor_sync(0xffffffffu, d0, 1);
            d0 += __shfl_xor_sync(0xffffffffu, d0, 2);
            d1 += __shfl_xor_sync(0xffffffffu, d1, 1);
            d1 += __shfl_xor_sync(0xffffffffu, d1, 2);
            if (lc == 0) {
                atomicAdd(&simS[wm * 32 + mt * 16 + lr], d0);
                atomicAdd(&simS[wm * 32 + mt * 16 + lr + 8], d1);
            }
        }
        __syncthreads();
        if (tid < 64) C[bm + tid] = simS[tid] * (1.f / 2048.f);
        return;
    }

    #pragma unroll
    for (int mt = 0; mt < 2; mt++) {
        int row = bm + wm * 32 + mt * 16 + lr;
        #pragma unroll
        for (int nt = 0; nt < 8; nt++) {
            int col = bn + wn * 64 + nt * 8 + 2 * lc;
            float2 b2 = *(const float2*)(bias + col);
            float* a = acc[mt][nt];
            a[0] += b2.x; a[1] += b2.y; a[2] += b2.x; a[3] += b2.y;
            if (mode == EP_LN || mode == EP_LN2) {
                float2 r0 = *(const float2*)(R + (size_t)row * ldc + col);
                float2 r1 = *(const float2*)(R + (size_t)(row + 8) * ldc + col);
                a[0] += r0.x; a[1] += r0.y; a[2] += r1.x; a[3] += r1.y;
            } else if (mode == EP_GELU) {
                a[0] = gelu_f(a[0]); a[1] = gelu_f(a[1]);
                a[2] = gelu_f(a[2]); a[3] = gelu_f(a[3]);
            } else if (mode == EP_FINAL) {
                float2 r0 = *(const float2*)(R + (size_t)row * ldc + col);
                float2 r1 = *(const float2*)(R + (size_t)(row + 8) * ldc + col);
                float sc0 = rs[row], sc1 = rs[row + 8];
                a[0] = r0.x + sc0 * a[0]; a[1] = r0.y + sc0 * a[1];
                a[2] = r1.x + sc1 * a[2]; a[3] = r1.y + sc1 * a[3];
            }
        }
    }

    if (mode == EP_LN || mode == EP_LN2 || mode == EP_COS) {
        float* ps = (float*)smem;        // [64][2]
        float* ps2 = ps + 128;
        #pragma unroll
        for (int mt = 0; mt < 2; mt++) {
            float p0 = 0.f, p1 = 0.f, q0 = 0.f, q1 = 0.f;
            #pragma unroll
            for (int nt = 0; nt < 8; nt++) {
                float* a = acc[mt][nt];
                p0 += a[0] + a[1]; q0 += a[0] * a[0] + a[1] * a[1];
                p1 += a[2] + a[3]; q1 += a[2] * a[2] + a[3] * a[3];
            }
            p0 += __shfl_xor_sync(0xffffffffu, p0, 1); p0 += __shfl_xor_sync(0xffffffffu, p0, 2);
            p1 += __shfl_xor_sync(0xffffffffu, p1, 1); p1 += __shfl_xor_sync(0xffffffffu, p1, 2);
            q0 += __shfl_xor_sync(0xffffffffu, q0, 1); q0 += __shfl_xor_sync(0xffffffffu, q0, 2);
            q1 += __shfl_xor_sync(0xffffffffu, q1, 1); q1 += __shfl_xor_sync(0xffffffffu, q1, 2);
            if (lc == 0) {
                int r0l = wm * 32 + mt * 16 + lr;
                ps[r0l * 2 + wn] = p0; ps2[r0l * 2 + wn] = q0;
                ps[(r0l + 8) * 2 + wn] = p1; ps2[(r0l + 8) * 2 + wn] = q1;
            }
        }
        __syncthreads();
        #pragma unroll
        for (int mt = 0; mt < 2; mt++) {
            int r0l = wm * 32 + mt * 16 + lr;
            float s0 = ps[r0l * 2] + ps[r0l * 2 + 1];
            float t0 = ps2[r0l * 2] + ps2[r0l * 2 + 1];
            float s1 = ps[(r0l + 8) * 2] + ps[(r0l + 8) * 2 + 1];
            float t1 = ps2[(r0l + 8) * 2] + ps2[(r0l + 8) * 2 + 1];
            int row0 = bm + r0l;
            if (mode == EP_COS) {
                float i0 = 1.f / fmaxf(sqrtf(t0), 1e-8f);
                float i1 = 1.f / fmaxf(sqrtf(t1), 1e-8f);
                #pragma unroll
                for (int nt = 0; nt < 8; nt++) {
                    int col = bn + wn * 64 + nt * 8 + 2 * lc;
                    float* a = acc[mt][nt];
                    size_t i0x = (size_t)row0 * ldc + col, i1x = (size_t)(row0 + 8) * ldc + col;
                    store_hl(Ch, Cl, i0x, a[0], a[1]);
                    store_hl(Ch, Cl, i1x, a[2], a[3]);
                    float n0 = a[0] * i0, n1 = a[1] * i0, n2 = a[2] * i1, n3 = a[3] * i1;
                    store_hl(C2h, C2l, i0x, n0, n1);
                    store_hl(C2h, C2l, i1x, n2, n3);
                    if (C) {
                        *(float2*)(C + i0x) = make_float2(n0, n1);
                        *(float2*)(C + i1x) = make_float2(n2, n3);
                    }
                }
            } else {
                float mu0 = s0 * (1.f / 128.f), mu1 = s1 * (1.f / 128.f);
                float rs0 = rsqrtf(t0 * (1.f / 128.f) - mu0 * mu0 + 1e-5f);
                float rs1 = rsqrtf(t1 * (1.f / 128.f) - mu1 * mu1 + 1e-5f);
                #pragma unroll
                for (int nt = 0; nt < 8; nt++) {
                    int col = bn + wn * 64 + nt * 8 + 2 * lc;
                    float* a = acc[mt][nt];
                    float2 g2 = *(const float2*)(gam + col);
                    float2 be2 = *(const float2*)(bet + col);
                    float w0 = (a[0] - mu0) * rs0 * g2.x + be2.x;
                    float w1 = (a[1] - mu0) * rs0 * g2.y + be2.y;
                    float w2 = (a[2] - mu1) * rs1 * g2.x + be2.x;
                    float w3 = (a[3] - mu1) * rs1 * g2.y + be2.y;
                    size_t i0x = (size_t)row0 * ldc + col, i1x = (size_t)(row0 + 8) * ldc + col;
                    *(float2*)(C + i0x) = make_float2(w0, w1);
                    *(float2*)(C + i1x) = make_float2(w2, w3);
                    if (Ch) {
                        store_hl(Ch, Cl, i0x, w0, w1);
                        store_hl(Ch, Cl, i1x, w2, w3);
                    }
                }
            }
        }
    } else {
        #pragma unroll
        for (int mt = 0; mt < 2; mt++) {
            int row = bm + wm * 32 + mt * 16 + lr;
            #pragma unroll
            for (int nt = 0; nt < 8; nt++) {
                int col = bn + wn * 64 + nt * 8 + 2 * lc;
                float* a = acc[mt][nt];
                size_t i0x = (size_t)row * ldc + col, i1x = (size_t)(row + 8) * ldc + col;
                if (mode == EP_GELU) {
                    store_hl(Ch, Cl, i0x, a[0], a[1]);
                    store_hl(Ch, Cl, i1x, a[2], a[3]);
                } else {
                    *(float2*)(C + i0x) = make_float2(a[0], a[1]);
                    *(float2*)(C + i1x) = make_float2(a[2], a[3]);
                }
            }
        }
    }
}

// ============== M covariance: M[b] += sn^T tn (contract over s) ==============
#define CST 34816
__global__ void __launch_bounds__(256) mcov_mma(
    const __nv_bfloat16* __restrict__ snh, const __nv_bfloat16* __restrict__ snl,
    const __nv_bfloat16* __restrict__ tnh, const __nv_bfloat16* __restrict__ tnl,
    float* __restrict__ M)
{
    extern __shared__ char smem[];
    uint32_t sb = smem_to_u32(smem);
    const int tid = threadIdx.x, lane = tid & 31, wid = tid >> 5;
    const int wm = wid >> 2, wn = wid & 3;
    const int lr = lane >> 2, lc = lane & 3;
    const int b = blockIdx.y, split = blockIdx.x;

    const int r = tid >> 3, q = tid & 7;
    const size_t srow0 = (size_t)b * SS + split * 128;
    const size_t gIdx = (srow0 + r) * 128 + q * 16;
    const __nv_bfloat16 *pSh = snh + gIdx, *pSl = snl + gIdx;
    const __nv_bfloat16 *pTh = tnh + gIdx, *pTl = tnl + gIdx;
    const uint32_t dBase = sb + r * 272 + q * 32;

    float acc[4][4][4];
    #pragma unroll
    for (int i = 0; i < 4; i++)
        #pragma unroll
        for (int j = 0; j < 4; j++)
            #pragma unroll
            for (int k = 0; k < 4; k++) acc[i][j][k] = 0.f;

    {
        uint32_t d = dBase;
        CP16(d, pSh); CP16(d + 16, pSh + 8);
        CP16(d + 8704, pSl); CP16(d + 8704 + 16, pSl + 8);
        CP16(d + 17408, pTh); CP16(d + 17408 + 16, pTh + 8);
        CP16(d + 26112, pTl); CP16(d + 26112 + 16, pTl + 8);
        CP_COMMIT();
    }

    for (int c = 0; c < 4; c++) {
        if (c + 1 < 4) {
            uint32_t d = dBase + ((c + 1) & 1) * CST;
            const size_t co = (size_t)(c + 1) * 32 * 128;
            CP16(d, pSh + co); CP16(d + 16, pSh + co + 8);
            CP16(d + 8704, pSl + co); CP16(d + 8704 + 16, pSl + co + 8);
            CP16(d + 17408, pTh + co); CP16(d + 17408 + 16, pTh + co + 8);
            CP16(d + 26112, pTl + co); CP16(d + 26112 + 16, pTl + co + 8);
            CP_COMMIT();
            CP_WAIT(1);
        } else {
            CP_WAIT(0);
        }
        __syncthreads();
        uint32_t base = sb + (c & 1) * CST;
        #pragma unroll
        for (int ks = 0; ks < 2; ks++) {
            uint32_t ah[4][4], al[4][4], bh[4][2], bl[4][2];
            #pragma unroll
            for (int mt = 0; mt < 4; mt++) {
                int rowk = ks * 16 + (lane & 7) + ((lane >> 4) & 1) * 8;
                int colm = wm * 64 + mt * 16 + ((lane >> 3) & 1) * 8;
                uint32_t addr = base + (uint32_t)(rowk * 272 + colm * 2);
                LDSM4T(ah[mt][0], ah[mt][1], ah[mt][2], ah[mt][3], addr);
                LDSM4T(al[mt][0], al[mt][1], al[mt][2], al[mt][3], addr + 8704);
            }
            #pragma unroll
            for (int nt = 0; nt < 4; nt++) {
                int rowk = ks * 16 + (lane & 15);
                int coln = wn * 32 + nt * 8;
                uint32_t addr = base + 17408 + (uint32_t)(rowk * 272 + coln * 2);
                LDSM2T(bh[nt][0], bh[nt][1], addr);
                LDSM2T(bl[nt][0], bl[nt][1], addr + 8704);
            }
            #pragma unroll
            for (int mt = 0; mt < 4; mt++)
                #pragma unroll
                for (int nt = 0; nt < 4; nt++) {
                    MMA_BF16(acc[mt][nt], ah[mt], bh[nt]);
                    MMA_BF16(acc[mt][nt], ah[mt], bl[nt]);
                    MMA_BF16(acc[mt][nt], al[mt], bh[nt]);
                }
        }
        __syncthreads();
    }

    float* Mb = M + (size_t)b * 16384;
    #pragma unroll
    for (int mt = 0; mt < 4; mt++) {
        int row = wm * 64 + mt * 16 + lr;
        #pragma unroll
        for (int nt = 0; nt < 4; nt++) {
            int col = wn * 32 + nt * 8 + 2 * lc;
            atomicAdd(&Mb[(size_t)row * 128 + col], acc[mt][nt][0]);
            atomicAdd(&Mb[(size_t)row * 128 + col + 1], acc[mt][nt][1]);
            atomicAdd(&Mb[(size_t)(row + 8) * 128 + col], acc[mt][nt][2]);
            atomicAdd(&Mb[(size_t)(row + 8) * 128 + col + 1], acc[mt][nt][3]);
        }
    }
}

// ---------------- local windowed causal attention ----------------
__global__ __launch_bounds__(64) void lw_attn_k(const float* __restrict__ qkv,
                                                __nv_bfloat16* __restrict__ Ch,
                                                __nv_bfloat16* __restrict__ Cl)
{
    int g = blockIdx.x, h = blockIdx.y, i = threadIdx.x;
    __shared__ float ks[64][17];
    __shared__ float vs[64][17];
    size_t tbase = (size_t)g * 64;
    const float* kp = qkv + (tbase + i) * 384 + 128 + h * 16;
    const float* vp = kp + 128;
    #pragma unroll
    for (int d = 0; d < 16; d++) { ks[i][d] = kp[d]; vs[i][d] = vp[d]; }
    float q[16];
    const float* qp = qkv + (tbase + i) * 384 + h * 16;
    #pragma unroll
    for (int d = 0; d < 16; d++) q[d] = qp[d];
    __syncthreads();
    float sc[64];
    float mx = -1e30f;
    #pragma unroll
    for (int j = 0; j < 64; j++) {
        float dv = 0.f;
        #pragma unroll
        for (int d = 0; d < 16; d++) dv += q[d] * ks[j][d];
        sc[j] = (j <= i) ? dv * 0.25f : -INFINITY;
        mx = fmaxf(mx, sc[j]);
    }
    float sum = 0.f;
    #pragma unroll
    for (int j = 0; j < 64; j++) { float e = expf(sc[j] - mx); sc[j] = e; sum += e; }
    float o[16] = {};
    #pragma unroll
    for (int j = 0; j < 64; j++) {
        float w = sc[j];
        #pragma unroll
        for (int d = 0; d < 16; d++) o[d] += w * vs[j][d];
    }
    float inv = 1.f / sum;
    size_t ob = (tbase + i) * 128 + h * 16;
    #pragma unroll
    for (int d = 0; d < 16; d += 2)
        store_hl(Ch, Cl, ob + d, o[d] * inv, o[d + 1] * inv);
}

// ---------------- interaction MHA (len = B = 8) ----------------
__global__ __launch_bounds__(64) void int_attn_k(const float* __restrict__ qkv,
                                                 __nv_bfloat16* __restrict__ Ch,
                                                 __nv_bfloat16* __restrict__ Cl)
{
    int s = blockIdx.x, tid = threadIdx.x;
    __shared__ float kvs[8][256];
    for (int idx = tid; idx < 8 * 256; idx += 64) {
        int jb = idx >> 8, c = idx & 255;
        kvs[jb][c] = qkv[((size_t)jb * SS + s) * 384 + 128 + c];
    }
    __syncthreads();
    int h = tid >> 3, qb = tid & 7;
    float q[16];
    const float* qp = qkv + ((size_t)qb * SS + s) * 384 + h * 16;
    #pragma unroll
    for (int d = 0; d < 16; d++) q[d] = qp[d];
    float sc[8];
    float mx = -1e30f;
    #pragma unroll
    for (int jb = 0; jb < 8; jb++) {
        float dv = 0.f;
        #pragma unroll
        for (int d = 0; d < 16; d++) dv += q[d] * kvs[jb][h * 16 + d];
        sc[jb] = dv * 0.25f;
        mx = fmaxf(mx, sc[jb]);
    }
    float sum = 0.f;
    #pragma unroll
    for (int jb = 0; jb < 8; jb++) { float e = expf(sc[jb] - mx); sc[jb] = e; sum += e; }
    float o[16] = {};
    #pragma unroll
    for (int jb = 0; jb < 8; jb++) {
        float w = sc[jb];
        #pragma unroll
        for (int d = 0; d < 16; d++) o[d] += w * kvs[jb][128 + h * 16 + d];
    }
    float inv = 1.f / sum;
    size_t ob = ((size_t)qb * SS + s) * 128 + h * 16;
    #pragma unroll
    for (int d = 0; d < 16; d += 2)
        store_hl(Ch, Cl, ob + d, o[d] * inv, o[d + 1] * inv);
}

extern "C" void kernel_launch(void* const* d_in, const int* in_sizes, int n_in,
                              void* d_out, int out_size)
{
    const float* x        = (const float*)d_in[0];
    const float* sp       = (const float*)d_in[1];
    const float* tp       = (const float*)d_in[2];
    const float* lw_in_b  = (const float*)d_in[4];
    const float* lw_out_b = (const float*)d_in[6];
    const float* spat_b   = (const float*)d_in[8];
    const float* temp_b   = (const float*)d_in[10];
    const float* int_in_b = (const float*)d_in[12];
    const float* int_out_b= (const float*)d_in[14];
    const float* ffn_b1   = (const float*)d_in[16];
    const float* ffn_b2   = (const float*)d_in[18];
    const float* ln1_g    = (const float*)d_in[19];
    const float* ln1_b    = (const float*)d_in[20];
    const float* ln2_g    = (const float*)d_in[21];
    const float* ln2_b    = (const float*)d_in[22];
    float* out = (float*)d_out;

    float* f32 = nullptr;
    __nv_bfloat16* bf = nullptr;
    cudaGetSymbolAddress((void**)&f32, g_f32);
    cudaGetSymbolAddress((void**)&bf, g_bf);

    static cudaStream_t s2 = nullptr;
    static cudaEvent_t evF = nullptr, evJ = nullptr;
    static bool init_done = false;
    if (!init_done) {
        cudaFuncSetAttribute(gemm_mma, cudaFuncAttributeMaxDynamicSharedMemorySize, 2 * GST);
        cudaFuncSetAttribute(mcov_mma, cudaFuncAttributeMaxDynamicSharedMemorySize, 2 * CST);
        cudaStreamCreateWithFlags(&s2, cudaStreamNonBlocking);
        cudaEventCreateWithFlags(&evF, cudaEventDisableTiming);
        cudaEventCreateWithFlags(&evJ, cudaEventDisableTiming);
        init_done = true;
    }

    float* qkv   = f32 + F_QKV;
    float* qkv2  = f32 + F_QKV2;
    float* bufb  = f32 + F_BUFB;
    float* bufc  = f32 + F_BUFC;
    float* snf   = f32 + F_SNF;
    float* bM    = f32 + F_M;
    float* bsim  = f32 + F_SIM;

    #define BH(o) (bf + (o))
    #define BL(o, n) (bf + (o) + (n))
    const unsigned NT = 2097152;

    // ---- fork point ----
    cudaEventRecord(evF, 0);
    cudaStreamWaitEvent(s2, evF, 0);

    // ===== main stream: x-chain =====
    {
        CvtSrc cs;
        cs.cnt = 5;
        cs.p[0] = x;                         cs.n[0] = 2097152; cs.off[0] = H_X;
        cs.p[1] = (const float*)d_in[3];     cs.n[1] = 49152;   cs.off[1] = H_LWIN;
        cs.p[2] = (const float*)d_in[5];     cs.n[2] = 16384;   cs.off[2] = H_LWOUT;
        cs.p[3] = (const float*)d_in[15];    cs.n[3] = 65536;   cs.off[3] = H_FW1;
        cs.p[4] = (const float*)d_in[17];    cs.n[4] = 65536;   cs.off[4] = H_FW2;
        cvt_k<<<296, 256>>>(cs);
    }
    gemm_mma<<<dim3(3, 256), 128, 2 * GST>>>(
        BH(H_X), BL(H_X, NT), nullptr, nullptr, BH(H_LWIN), BL(H_LWIN, 49152),
        lw_in_b, qkv, nullptr, nullptr, nullptr, nullptr, nullptr, nullptr,
        nullptr, nullptr, 128, 384, EP_F32, 0);
    lw_attn_k<<<dim3(256, 8), 64>>>(qkv, BH(H_ATT), BL(H_ATT, NT));
    gemm_mma<<<dim3(1, 256), 128, 2 * GST>>>(
        BH(H_ATT), BL(H_ATT, NT), nullptr, nullptr, BH(H_LWOUT), BL(H_LWOUT, 16384),
        lw_out_b, bufb, BH(H_BUFB), BL(H_BUFB, NT), nullptr, nullptr,
        x, nullptr, ln1_g, ln1_b, 128, 128, EP_LN, 0);
    gemm_mma<<<dim3(4, 256), 128, 2 * GST>>>(
        BH(H_BUFB), BL(H_BUFB, NT), nullptr, nullptr, BH(H_FW1), BL(H_FW1, 65536),
        ffn_b1, nullptr, BH(H_BUFH), BL(H_BUFH, 8388608), nullptr, nullptr,
        nullptr, nullptr, nullptr, nullptr, 128, 512, EP_GELU, 0);
    gemm_mma<<<dim3(1, 256), 128, 2 * GST>>>(
        BH(H_BUFH), BL(H_BUFH, 8388608), nullptr, nullptr, BH(H_FW2), BL(H_FW2, 65536),
        ffn_b2, bufc, nullptr, nullptr, nullptr, nullptr,
        bufb, nullptr, ln2_g, ln2_b, 512, 128, EP_LN2, 0);

    // ===== stream 2: spatio-temporal chain =====
    {
        CvtSrc cs;
        cs.cnt = 6;
        cs.p[0] = sp;                        cs.n[0] = 2097152; cs.off[0] = H_SP;
        cs.p[1] = tp;                        cs.n[1] = 2097152; cs.off[1] = H_TP;
        cs.p[2] = (const float*)d_in[7];     cs.n[2] = 16384;   cs.off[2] = H_SPATW;
        cs.p[3] = (const float*)d_in[9];     cs.n[3] = 16384;   cs.off[3] = H_TEMPW;
        cs.p[4] = (const float*)d_in[11];    cs.n[4] = 49152;   cs.off[4] = H_INTIN;
        cs.p[5] = (const float*)d_in[13];    cs.n[5] = 16384;   cs.off[5] = H_INTOUT;
        cvt_k<<<296, 256, 0, s2>>>(cs);
    }
    zero_k<<<512, 256, 0, s2>>>(bM, 8 * 128 * 128);
    gemm_mma<<<dim3(1, 256), 128, 2 * GST, s2>>>(
        BH(H_SP), BL(H_SP, NT), nullptr, nullptr, BH(H_SPATW), BL(H_SPATW, 16384),
        spat_b, snf, BH(H_SE), BL(H_SE, NT), BH(H_SN), BL(H_SN, NT),
        nullptr, nullptr, nullptr, nullptr, 128, 128, EP_COS, 0);
    gemm_mma<<<dim3(1, 256), 128, 2 * GST, s2>>>(
        BH(H_TP), BL(H_TP, NT), nullptr, nullptr, BH(H_TEMPW), BL(H_TEMPW, 16384),
        temp_b, nullptr, BH(H_TE), BL(H_TE, NT), BH(H_TN), BL(H_TN, NT),
        nullptr, nullptr, nullptr, nullptr, 128, 128, EP_COS, 0);
    mcov_mma<<<dim3(16, 8), 256, 2 * CST, s2>>>(
        BH(H_SN), BL(H_SN, NT), BH(H_TN), BL(H_TN, NT), bM);
    cvtm_k<<<128, 256, 0, s2>>>(bM, BH(H_M), BL(H_M, 131072), 131072);
    gemm_mma<<<dim3(1, 256), 128, 2 * GST, s2>>>(
        BH(H_TN), BL(H_TN, NT), nullptr, nullptr, BH(H_M), BL(H_M, 131072),
        nullptr, bsim, nullptr, nullptr, nullptr, nullptr,
        snf, nullptr, nullptr, nullptr, 128, 0, EP_SIMDOT, 16384);
    gemm_mma<<<dim3(3, 256), 128, 2 * GST, s2>>>(
        BH(H_SE), BL(H_SE, NT), BH(H_TE), BL(H_TE, NT), BH(H_INTIN), BL(H_INTIN, 49152),
        int_in_b, qkv2, nullptr, nullptr, nullptr, nullptr, nullptr, nullptr,
        nullptr, nullptr, 128, 384, EP_F32, 0);
    int_attn_k<<<SS, 64, 0, s2>>>(qkv2, BH(H_ATT2), BL(H_ATT2, NT));
    cudaEventRecord(evJ, s2);

    // ---- join + final ----
    cudaStreamWaitEvent(0, evJ, 0);
    gemm_mma<<<dim3(1, 256), 128, 2 * GST>>>(
        BH(H_ATT2), BL(H_ATT2, NT), nullptr, nullptr, BH(H_INTOUT), BL(H_INTOUT, 16384),
        int_out_b, out, nullptr, nullptr, nullptr, nullptr,
        bufc, bsim, nullptr, nullptr, 128, 128, EP_FINAL, 0);
}

// round 7
// speedup vs baseline: 2.7385x; 1.1089x over previous
#include <cuda_runtime.h>
#include <cuda_bf16.h>
#include <cstdint>
#include <math.h>

#define BB 8
#define SS 2048
#define TT 16384

// ---------------- float scratch ----------------
#define F_QKV  0u          // 16384*384
#define F_BUFB 6291456u    // 16384*128
#define F_BUFC 8388608u
#define F_SNF  10485760u
#define F_M    12582912u   // 8*128*128
#define F_SIM  12713984u   // 16384 (contiguous after F_M)
#define F_QKV2 12730368u   // 16384*384
#define F_TOT  19021824u
__device__ float g_f32[F_TOT];

// ---------------- bf16 scratch (each tensor: HI then LO contiguous) ----------------
#define H_X      0u
#define H_SP     4194304u
#define H_TP     8388608u
#define H_ATT    12582912u
#define H_BUFB   16777216u
#define H_BUFH   20971520u   // 16384*512 *2
#define H_SE     37748736u
#define H_SN     41943040u
#define H_TE     46137344u
#define H_TN     50331648u
#define H_M      54525952u   // 131072*2
#define H_LWIN   54788096u   // 49152*2
#define H_LWOUT  54886400u   // 16384*2
#define H_SPATW  54919168u
#define H_TEMPW  54951936u
#define H_INTIN  54984704u   // 49152*2
#define H_INTOUT 55083008u
#define H_FW1    55115776u   // 65536*2
#define H_FW2    55246848u
#define H_ATT2   55377920u   // 2097152*2
#define BF_TOT   59572224u
__device__ __nv_bfloat16 g_bf[BF_TOT];

enum { EP_F32 = 0, EP_LN = 1, EP_GELU = 2, EP_LN2 = 3, EP_COS = 4, EP_FINAL = 5, EP_SIMDOT = 6 };

__device__ __forceinline__ uint32_t smem_to_u32(const void* p) {
    uint32_t a;
    asm("{ .reg .u64 t; cvta.to.shared.u64 t, %1; cvt.u32.u64 %0, t; }" : "=r"(a) : "l"(p));
    return a;
}

#define CP16(dst, src) do { \
    unsigned long long _gs = (unsigned long long)__cvta_generic_to_global((const void*)(src)); \
    asm volatile("cp.async.cg.shared.global [%0], [%1], 16;" :: "r"(dst), "l"(_gs)); } while (0)
#define CP_COMMIT() asm volatile("cp.async.commit_group;" ::: "memory")
#define CP_WAIT(n) asm volatile("cp.async.wait_group %0;" :: "n"(n) : "memory")

#define LDSM4(r0, r1, r2, r3, addr) \
    asm volatile("ldmatrix.sync.aligned.m8n8.x4.shared.b16 {%0,%1,%2,%3}, [%4];" \
        : "=r"(r0), "=r"(r1), "=r"(r2), "=r"(r3) : "r"(addr))
#define LDSM4T(r0, r1, r2, r3, addr) \
    asm volatile("ldmatrix.sync.aligned.m8n8.x4.trans.shared.b16 {%0,%1,%2,%3}, [%4];" \
        : "=r"(r0), "=r"(r1), "=r"(r2), "=r"(r3) : "r"(addr))
#define LDSM2T(r0, r1, addr) \
    asm volatile("ldmatrix.sync.aligned.m8n8.x2.trans.shared.b16 {%0,%1}, [%2];" \
        : "=r"(r0), "=r"(r1) : "r"(addr))

#define MMA_BF16(c, a, b) \
    asm volatile("mma.sync.aligned.m16n8k16.row.col.f32.bf16.bf16.f32 " \
        "{%0,%1,%2,%3}, {%4,%5,%6,%7}, {%8,%9}, {%0,%1,%2,%3};" \
        : "+f"((c)[0]), "+f"((c)[1]), "+f"((c)[2]), "+f"((c)[3]) \
        : "r"((a)[0]), "r"((a)[1]), "r"((a)[2]), "r"((a)[3]), "r"((b)[0]), "r"((b)[1]))

__device__ __forceinline__ void cvt_split4(float4 v, uint2& hv, uint2& lv) {
    __nv_bfloat16 h0 = __float2bfloat16_rn(v.x);
    __nv_bfloat16 h1 = __float2bfloat16_rn(v.y);
    __nv_bfloat16 h2 = __float2bfloat16_rn(v.z);
    __nv_bfloat16 h3 = __float2bfloat16_rn(v.w);
    __nv_bfloat16 l0 = __float2bfloat16_rn(v.x - __bfloat162float(h0));
    __nv_bfloat16 l1 = __float2bfloat16_rn(v.y - __bfloat162float(h1));
    __nv_bfloat16 l2 = __float2bfloat16_rn(v.z - __bfloat162float(h2));
    __nv_bfloat16 l3 = __float2bfloat16_rn(v.w - __bfloat162float(h3));
    hv.x = (uint32_t)__bfloat16_as_ushort(h0) | ((uint32_t)__bfloat16_as_ushort(h1) << 16);
    hv.y = (uint32_t)__bfloat16_as_ushort(h2) | ((uint32_t)__bfloat16_as_ushort(h3) << 16);
    lv.x = (uint32_t)__bfloat16_as_ushort(l0) | ((uint32_t)__bfloat16_as_ushort(l1) << 16);
    lv.y = (uint32_t)__bfloat16_as_ushort(l2) | ((uint32_t)__bfloat16_as_ushort(l3) << 16);
}

__device__ __forceinline__ void store_hl(__nv_bfloat16* Ch, __nv_bfloat16* Cl,
                                         size_t idx, float w0, float w1) {
    __nv_bfloat16 h0 = __float2bfloat16_rn(w0), h1 = __float2bfloat16_rn(w1);
    __nv_bfloat162 hp; hp.x = h0; hp.y = h1;
    *(__nv_bfloat162*)(Ch + idx) = hp;
    __nv_bfloat162 lp;
    lp.x = __float2bfloat16_rn(w0 - __bfloat162float(h0));
    lp.y = __float2bfloat16_rn(w1 - __bfloat162float(h1));
    *(__nv_bfloat162*)(Cl + idx) = lp;
}

__device__ __forceinline__ float gelu_f(float v) {
    return 0.5f * v * (1.0f + erff(v * 0.70710678118654752f));
}

// ============== pre-split conversion ==============
struct CvtSrc { const float* p[6]; int n[6]; unsigned off[6]; int cnt; };
__global__ void __launch_bounds__(256) cvt_k(CvtSrc s)
{
    int stride = gridDim.x * blockDim.x;
    int t = blockIdx.x * blockDim.x + threadIdx.x;
    for (int seg = 0; seg < s.cnt; seg++) {
        const float4* src = (const float4*)s.p[seg];
        __nv_bfloat16* dh = g_bf + s.off[seg];
        __nv_bfloat16* dl = dh + s.n[seg];
        int m = s.n[seg] >> 2;
        for (int i = t; i < m; i += stride) {
            uint2 hv, lv;
            cvt_split4(src[i], hv, lv);
            *(uint2*)(dh + (size_t)i * 4) = hv;
            *(uint2*)(dl + (size_t)i * 4) = lv;
        }
    }
}

__global__ void __launch_bounds__(256) cvtm_k(const float* __restrict__ src,
                                              __nv_bfloat16* dh, __nv_bfloat16* dl, int n)
{
    int t = blockIdx.x * blockDim.x + threadIdx.x;
    int m = n >> 2;
    for (int i = t; i < m; i += gridDim.x * blockDim.x) {
        uint2 hv, lv;
        cvt_split4(((const float4*)src)[i], hv, lv);
        *(uint2*)(dh + (size_t)i * 4) = hv;
        *(uint2*)(dl + (size_t)i * 4) = lv;
    }
}

__global__ void zero_k(float* p, int n)
{
    int i = blockIdx.x * 256 + threadIdx.x;
    if (i < n) p[i] = 0.f;
}

// ============== generic bf16-split GEMM: C[M,N] = A @ W^T ==============
// Tile 64(M) x 128(N), 256 threads = 8 warps (2 wm x 4 wn), warp tile 32x32.
// smem stage (30720B): AH +0 (64x80), AL +5120, BH +10240 (128x80), BL +20480.
#define GST 30720
__global__ void __launch_bounds__(256, 3) gemm_mma(
    const __nv_bfloat16* __restrict__ Ah, const __nv_bfloat16* __restrict__ Al,
    const __nv_bfloat16* __restrict__ A2h, const __nv_bfloat16* __restrict__ A2l,
    const __nv_bfloat16* __restrict__ Wh, const __nv_bfloat16* __restrict__ Wl,
    const float* __restrict__ bias, float* __restrict__ C,
    __nv_bfloat16* __restrict__ Ch, __nv_bfloat16* __restrict__ Cl,
    __nv_bfloat16* __restrict__ C2h, __nv_bfloat16* __restrict__ C2l,
    const float* __restrict__ R, const float* __restrict__ rs,
    const float* __restrict__ gam, const float* __restrict__ bet,
    int K, int ldc, int mode, int batchW)
{
    extern __shared__ char smem[];
    uint32_t sb = smem_to_u32(smem);
    const int tid = threadIdx.x, lane = tid & 31, wid = tid >> 5;
    const int wm = wid >> 2, wn = wid & 3;
    const int lr = lane >> 2, lc = lane & 3;
    const int bm = blockIdx.y * 64, bn = blockIdx.x * 128;

    const __nv_bfloat16* Auh = (A2h && bn > 0) ? A2h : Ah;
    const __nv_bfloat16* Aul = (A2h && bn > 0) ? A2l : Al;
    if (batchW) { Wh += (size_t)(bm >> 11) * (size_t)batchW; Wl += (size_t)(bm >> 11) * (size_t)batchW; }

    // A loader: 64 rows x 64B, one 16B quarter per thread
    const int ra = tid >> 2, qa = tid & 3;
    const size_t aIdx = (size_t)(bm + ra) * K + qa * 8;
    // B loader: 128 rows x 64B, one 32B half per thread
    const int rb = tid >> 1, hb = tid & 1;
    const size_t wIdx = (size_t)(bn + rb) * K + hb * 16;
    const __nv_bfloat16 *pAh = Auh + aIdx, *pAl = Aul + aIdx;
    const __nv_bfloat16 *pWh = Wh + wIdx, *pWl = Wl + wIdx;
    const uint32_t dA = sb + ra * 80 + qa * 16;
    const uint32_t dB = sb + 10240 + rb * 80 + hb * 32;

    float acc[2][4][4];
    #pragma unroll
    for (int i = 0; i < 2; i++)
        #pragma unroll
        for (int j = 0; j < 4; j++)
            #pragma unroll
            for (int k = 0; k < 4; k++) acc[i][j][k] = 0.f;

    const int nch = K >> 5;

    {
        CP16(dA, pAh); CP16(dA + 5120, pAl);
        CP16(dB, pWh); CP16(dB + 16, pWh + 8);
        CP16(dB + 10240, pWl); CP16(dB + 10240 + 16, pWl + 8);
        CP_COMMIT();
    }

    for (int c = 0; c < nch; c++) {
        if (c + 1 < nch) {
            uint32_t stg = ((c + 1) & 1) * GST;
            const int co = (c + 1) * 32;
            CP16(dA + stg, pAh + co); CP16(dA + stg + 5120, pAl + co);
            CP16(dB + stg, pWh + co); CP16(dB + stg + 16, pWh + co + 8);
            CP16(dB + stg + 10240, pWl + co); CP16(dB + stg + 10240 + 16, pWl + co + 8);
            CP_COMMIT();
            CP_WAIT(1);
        } else {
            CP_WAIT(0);
        }
        __syncthreads();
        uint32_t base = sb + (c & 1) * GST;
        #pragma unroll
        for (int ks = 0; ks < 2; ks++) {
            uint32_t ah[2][4], al[2][4], bh[4][2], bl[4][2];
            #pragma unroll
            for (int mt = 0; mt < 2; mt++) {
                uint32_t addr = base + (uint32_t)((wm * 32 + mt * 16 + (lane & 15)) * 80
                               + ks * 32 + ((lane >> 4) & 1) * 16);
                LDSM4(ah[mt][0], ah[mt][1], ah[mt][2], ah[mt][3], addr);
                LDSM4(al[mt][0], al[mt][1], al[mt][2], al[mt][3], addr + 5120);
            }
            #pragma unroll
            for (int ntp = 0; ntp < 2; ntp++) {
                int colrow = wn * 32 + ntp * 16 + ((lane >> 4) & 1) * 8 + (lane & 7);
                uint32_t addr = base + 10240 + (uint32_t)(colrow * 80
                               + ks * 32 + ((lane >> 3) & 1) * 16);
                LDSM4(bh[2 * ntp][0], bh[2 * ntp][1], bh[2 * ntp + 1][0], bh[2 * ntp + 1][1], addr);
                LDSM4(bl[2 * ntp][0], bl[2 * ntp][1], bl[2 * ntp + 1][0], bl[2 * ntp + 1][1], addr + 10240);
            }
            #pragma unroll
            for (int mt = 0; mt < 2; mt++)
                #pragma unroll
                for (int nt = 0; nt < 4; nt++) {
                    MMA_BF16(acc[mt][nt], ah[mt], bh[nt]);
                    MMA_BF16(acc[mt][nt], ah[mt], bl[nt]);
                    MMA_BF16(acc[mt][nt], al[mt], bh[nt]);
                }
        }
        __syncthreads();
    }

    // ---------------- epilogues ----------------
    if (mode == EP_SIMDOT) {
        float* simS = (float*)smem;
        if (tid < 64) simS[tid] = 0.f;
        __syncthreads();
        #pragma unroll
        for (int mt = 0; mt < 2; mt++) {
            int row0 = bm + wm * 32 + mt * 16 + lr;
            float d0 = 0.f, d1 = 0.f;
            #pragma unroll
            for (int nt = 0; nt < 4; nt++) {
                int col = bn + wn * 32 + nt * 8 + 2 * lc;
                float2 s0 = *(const float2*)(R + (size_t)row0 * 128 + col);
                float2 s1 = *(const float2*)(R + (size_t)(row0 + 8) * 128 + col);
                d0 += acc[mt][nt][0] * s0.x + acc[mt][nt][1] * s0.y;
                d1 += acc[mt][nt][2] * s1.x + acc[mt][nt][3] * s1.y;
            }
            d0 += __shfl_xor_sync(0xffffffffu, d0, 1);
            d0 += __shfl_xor_sync(0xffffffffu, d0, 2);
            d1 += __shfl_xor_sync(0xffffffffu, d1, 1);
            d1 += __shfl_xor_sync(0xffffffffu, d1, 2);
            if (lc == 0) {
                atomicAdd(&simS[wm * 32 + mt * 16 + lr], d0);
                atomicAdd(&simS[wm * 32 + mt * 16 + lr + 8], d1);
            }
        }
        __syncthreads();
        if (tid < 64) C[bm + tid] = simS[tid] * (1.f / 2048.f);
        return;
    }

    #pragma unroll
    for (int mt = 0; mt < 2; mt++) {
        int row = bm + wm * 32 + mt * 16 + lr;
        #pragma unroll
        for (int nt = 0; nt < 4; nt++) {
            int col = bn + wn * 32 + nt * 8 + 2 * lc;
            float2 b2 = *(const float2*)(bias + col);
            float* a = acc[mt][nt];
            a[0] += b2.x; a[1] += b2.y; a[2] += b2.x; a[3] += b2.y;
            if (mode == EP_LN || mode == EP_LN2) {
                float2 r0 = *(const float2*)(R + (size_t)row * ldc + col);
                float2 r1 = *(const float2*)(R + (size_t)(row + 8) * ldc + col);
                a[0] += r0.x; a[1] += r0.y; a[2] += r1.x; a[3] += r1.y;
            } else if (mode == EP_GELU) {
                a[0] = gelu_f(a[0]); a[1] = gelu_f(a[1]);
                a[2] = gelu_f(a[2]); a[3] = gelu_f(a[3]);
            } else if (mode == EP_FINAL) {
                float2 r0 = *(const float2*)(R + (size_t)row * ldc + col);
                float2 r1 = *(const float2*)(R + (size_t)(row + 8) * ldc + col);
                float sc0 = rs[row], sc1 = rs[row + 8];
                a[0] = r0.x + sc0 * a[0]; a[1] = r0.y + sc0 * a[1];
                a[2] = r1.x + sc1 * a[2]; a[3] = r1.y + sc1 * a[3];
            }
        }
    }

    if (mode == EP_LN || mode == EP_LN2 || mode == EP_COS) {
        float* ps = (float*)smem;        // [64][4]
        float* ps2 = ps + 256;
        #pragma unroll
        for (int mt = 0; mt < 2; mt++) {
            float p0 = 0.f, p1 = 0.f, q0 = 0.f, q1 = 0.f;
            #pragma unroll
            for (int nt = 0; nt < 4; nt++) {
                float* a = acc[mt][nt];
                p0 += a[0] + a[1]; q0 += a[0] * a[0] + a[1] * a[1];
                p1 += a[2] + a[3]; q1 += a[2] * a[2] + a[3] * a[3];
            }
            p0 += __shfl_xor_sync(0xffffffffu, p0, 1); p0 += __shfl_xor_sync(0xffffffffu, p0, 2);
            p1 += __shfl_xor_sync(0xffffffffu, p1, 1); p1 += __shfl_xor_sync(0xffffffffu, p1, 2);
            q0 += __shfl_xor_sync(0xffffffffu, q0, 1); q0 += __shfl_xor_sync(0xffffffffu, q0, 2);
            q1 += __shfl_xor_sync(0xffffffffu, q1, 1); q1 += __shfl_xor_sync(0xffffffffu, q1, 2);
            if (lc == 0) {
                int r0l = wm * 32 + mt * 16 + lr;
                ps[r0l * 4 + wn] = p0; ps2[r0l * 4 + wn] = q0;
                ps[(r0l + 8) * 4 + wn] = p1; ps2[(r0l + 8) * 4 + wn] = q1;
            }
        }
        __syncthreads();
        #pragma unroll
        for (int mt = 0; mt < 2; mt++) {
            int r0l = wm * 32 + mt * 16 + lr;
            float s0 = 0.f, t0 = 0.f, s1 = 0.f, t1 = 0.f;
            #pragma unroll
            for (int w4 = 0; w4 < 4; w4++) {
                s0 += ps[r0l * 4 + w4]; t0 += ps2[r0l * 4 + w4];
                s1 += ps[(r0l + 8) * 4 + w4]; t1 += ps2[(r0l + 8) * 4 + w4];
            }
            int row0 = bm + r0l;
            if (mode == EP_COS) {
                float i0 = 1.f / fmaxf(sqrtf(t0), 1e-8f);
                float i1 = 1.f / fmaxf(sqrtf(t1), 1e-8f);
                #pragma unroll
                for (int nt = 0; nt < 4; nt++) {
                    int col = bn + wn * 32 + nt * 8 + 2 * lc;
                    float* a = acc[mt][nt];
                    size_t i0x = (size_t)row0 * ldc + col, i1x = (size_t)(row0 + 8) * ldc + col;
                    store_hl(Ch, Cl, i0x, a[0], a[1]);
                    store_hl(Ch, Cl, i1x, a[2], a[3]);
                    float n0 = a[0] * i0, n1 = a[1] * i0, n2 = a[2] * i1, n3 = a[3] * i1;
                    store_hl(C2h, C2l, i0x, n0, n1);
                    store_hl(C2h, C2l, i1x, n2, n3);
                    if (C) {
                        *(float2*)(C + i0x) = make_float2(n0, n1);
                        *(float2*)(C + i1x) = make_float2(n2, n3);
                    }
                }
            } else {
                float mu0 = s0 * (1.f / 128.f), mu1 = s1 * (1.f / 128.f);
                float rs0 = rsqrtf(t0 * (1.f / 128.f) - mu0 * mu0 + 1e-5f);
                float rs1 = rsqrtf(t1 * (1.f / 128.f) - mu1 * mu1 + 1e-5f);
                #pragma unroll
                for (int nt = 0; nt < 4; nt++) {
                    int col = bn + wn * 32 + nt * 8 + 2 * lc;
                    float* a = acc[mt][nt];
                    float2 g2 = *(const float2*)(gam + col);
                    float2 be2 = *(const float2*)(bet + col);
                    float w0 = (a[0] - mu0) * rs0 * g2.x + be2.x;
                    float w1 = (a[1] - mu0) * rs0 * g2.y + be2.y;
                    float w2 = (a[2] - mu1) * rs1 * g2.x + be2.x;
                    float w3 = (a[3] - mu1) * rs1 * g2.y + be2.y;
                    size_t i0x = (size_t)row0 * ldc + col, i1x = (size_t)(row0 + 8) * ldc + col;
                    *(float2*)(C + i0x) = make_float2(w0, w1);
                    *(float2*)(C + i1x) = make_float2(w2, w3);
                    if (Ch) {
                        store_hl(Ch, Cl, i0x, w0, w1);
                        store_hl(Ch, Cl, i1x, w2, w3);
                    }
                }
            }
        }
    } else {
        #pragma unroll
        for (int mt = 0; mt < 2; mt++) {
            int row = bm + wm * 32 + mt * 16 + lr;
            #pragma unroll
            for (int nt = 0; nt < 4; nt++) {
                int col = bn + wn * 32 + nt * 8 + 2 * lc;
                float* a = acc[mt][nt];
                size_t i0x = (size_t)row * ldc + col, i1x = (size_t)(row + 8) * ldc + col;
                if (mode == EP_GELU) {
                    store_hl(Ch, Cl, i0x, a[0], a[1]);
                    store_hl(Ch, Cl, i1x, a[2], a[3]);
                } else {
                    *(float2*)(C + i0x) = make_float2(a[0], a[1]);
                    *(float2*)(C + i1x) = make_float2(a[2], a[3]);
                }
            }
        }
    }
}

// ============== M covariance: M[b] += sn^T tn (contract over s) ==============
#define CST 34816
__global__ void __launch_bounds__(256) mcov_mma(
    const __nv_bfloat16* __restrict__ snh, const __nv_bfloat16* __restrict__ snl,
    const __nv_bfloat16* __restrict__ tnh, const __nv_bfloat16* __restrict__ tnl,
    float* __restrict__ M)
{
    extern __shared__ char smem[];
    uint32_t sb = smem_to_u32(smem);
    const int tid = threadIdx.x, lane = tid & 31, wid = tid >> 5;
    const int wm = wid >> 2, wn = wid & 3;
    const int lr = lane >> 2, lc = lane & 3;
    const int b = blockIdx.y, split = blockIdx.x;

    const int r = tid >> 3, q = tid & 7;
    const size_t srow0 = (size_t)b * SS + split * 128;
    const size_t gIdx = (srow0 + r) * 128 + q * 16;
    const __nv_bfloat16 *pSh = snh + gIdx, *pSl = snl + gIdx;
    const __nv_bfloat16 *pTh = tnh + gIdx, *pTl = tnl + gIdx;
    const uint32_t dBase = sb + r * 272 + q * 32;

    float acc[4][4][4];
    #pragma unroll
    for (int i = 0; i < 4; i++)
        #pragma unroll
        for (int j = 0; j < 4; j++)
            #pragma unroll
            for (int k = 0; k < 4; k++) acc[i][j][k] = 0.f;

    {
        uint32_t d = dBase;
        CP16(d, pSh); CP16(d + 16, pSh + 8);
        CP16(d + 8704, pSl); CP16(d + 8704 + 16, pSl + 8);
        CP16(d + 17408, pTh); CP16(d + 17408 + 16, pTh + 8);
        CP16(d + 26112, pTl); CP16(d + 26112 + 16, pTl + 8);
        CP_COMMIT();
    }

    for (int c = 0; c < 4; c++) {
        if (c + 1 < 4) {
            uint32_t d = dBase + ((c + 1) & 1) * CST;
            const size_t co = (size_t)(c + 1) * 32 * 128;
            CP16(d, pSh + co); CP16(d + 16, pSh + co + 8);
            CP16(d + 8704, pSl + co); CP16(d + 8704 + 16, pSl + co + 8);
            CP16(d + 17408, pTh + co); CP16(d + 17408 + 16, pTh + co + 8);
            CP16(d + 26112, pTl + co); CP16(d + 26112 + 16, pTl + co + 8);
            CP_COMMIT();
            CP_WAIT(1);
        } else {
            CP_WAIT(0);
        }
        __syncthreads();
        uint32_t base = sb + (c & 1) * CST;
        #pragma unroll
        for (int ks = 0; ks < 2; ks++) {
            uint32_t ah[4][4], al[4][4], bh[4][2], bl[4][2];
            #pragma unroll
            for (int mt = 0; mt < 4; mt++) {
                int rowk = ks * 16 + (lane & 7) + ((lane >> 4) & 1) * 8;
                int colm = wm * 64 + mt * 16 + ((lane >> 3) & 1) * 8;
                uint32_t addr = base + (uint32_t)(rowk * 272 + colm * 2);
                LDSM4T(ah[mt][0], ah[mt][1], ah[mt][2], ah[mt][3], addr);
                LDSM4T(al[mt][0], al[mt][1], al[mt][2], al[mt][3], addr + 8704);
            }
            #pragma unroll
            for (int nt = 0; nt < 4; nt++) {
                int rowk = ks * 16 + (lane & 15);
                int coln = wn * 32 + nt * 8;
                uint32_t addr = base + 17408 + (uint32_t)(rowk * 272 + coln * 2);
                LDSM2T(bh[nt][0], bh[nt][1], addr);
                LDSM2T(bl[nt][0], bl[nt][1], addr + 8704);
            }
            #pragma unroll
            for (int mt = 0; mt < 4; mt++)
                #pragma unroll
                for (int nt = 0; nt < 4; nt++) {
                    MMA_BF16(acc[mt][nt], ah[mt], bh[nt]);
                    MMA_BF16(acc[mt][nt], ah[mt], bl[nt]);
                    MMA_BF16(acc[mt][nt], al[mt], bh[nt]);
                }
        }
        __syncthreads();
    }

    float* Mb = M + (size_t)b * 16384;
    #pragma unroll
    for (int mt = 0; mt < 4; mt++) {
        int row = wm * 64 + mt * 16 + lr;
        #pragma unroll
        for (int nt = 0; nt < 4; nt++) {
            int col = wn * 32 + nt * 8 + 2 * lc;
            atomicAdd(&Mb[(size_t)row * 128 + col], acc[mt][nt][0]);
            atomicAdd(&Mb[(size_t)row * 128 + col + 1], acc[mt][nt][1]);
            atomicAdd(&Mb[(size_t)(row + 8) * 128 + col], acc[mt][nt][2]);
            atomicAdd(&Mb[(size_t)(row + 8) * 128 + col + 1], acc[mt][nt][3]);
        }
    }
}

// ---------------- local windowed causal attention ----------------
__global__ __launch_bounds__(64) void lw_attn_k(const float* __restrict__ qkv,
                                                __nv_bfloat16* __restrict__ Ch,
                                                __nv_bfloat16* __restrict__ Cl)
{
    int g = blockIdx.x, h = blockIdx.y, i = threadIdx.x;
    __shared__ float ks[64][17];
    __shared__ float vs[64][17];
    size_t tbase = (size_t)g * 64;
    const float* kp = qkv + (tbase + i) * 384 + 128 + h * 16;
    const float* vp = kp + 128;
    #pragma unroll
    for (int d = 0; d < 16; d++) { ks[i][d] = kp[d]; vs[i][d] = vp[d]; }
    float q[16];
    const float* qp = qkv + (tbase + i) * 384 + h * 16;
    #pragma unroll
    for (int d = 0; d < 16; d++) q[d] = qp[d];
    __syncthreads();
    float sc[64];
    float mx = -1e30f;
    #pragma unroll
    for (int j = 0; j < 64; j++) {
        float dv = 0.f;
        #pragma unroll
        for (int d = 0; d < 16; d++) dv += q[d] * ks[j][d];
        sc[j] = (j <= i) ? dv * 0.25f : -INFINITY;
        mx = fmaxf(mx, sc[j]);
    }
    float sum = 0.f;
    #pragma unroll
    for (int j = 0; j < 64; j++) { float e = expf(sc[j] - mx); sc[j] = e; sum += e; }
    float o[16] = {};
    #pragma unroll
    for (int j = 0; j < 64; j++) {
        float w = sc[j];
        #pragma unroll
        for (int d = 0; d < 16; d++) o[d] += w * vs[j][d];
    }
    float inv = 1.f / sum;
    size_t ob = (tbase + i) * 128 + h * 16;
    #pragma unroll
    for (int d = 0; d < 16; d += 2)
        store_hl(Ch, Cl, ob + d, o[d] * inv, o[d + 1] * inv);
}

// ---------------- interaction MHA (len = B = 8) ----------------
__global__ __launch_bounds__(64) void int_attn_k(const float* __restrict__ qkv,
                                                 __nv_bfloat16* __restrict__ Ch,
                                                 __nv_bfloat16* __restrict__ Cl)
{
    int s = blockIdx.x, tid = threadIdx.x;
    __shared__ float kvs[8][256];
    for (int idx = tid; idx < 8 * 256; idx += 64) {
        int jb = idx >> 8, c = idx & 255;
        kvs[jb][c] = qkv[((size_t)jb * SS + s) * 384 + 128 + c];
    }
    __syncthreads();
    int h = tid >> 3, qb = tid & 7;
    float q[16];
    const float* qp = qkv + ((size_t)qb * SS + s) * 384 + h * 16;
    #pragma unroll
    for (int d = 0; d < 16; d++) q[d] = qp[d];
    float sc[8];
    float mx = -1e30f;
    #pragma unroll
    for (int jb = 0; jb < 8; jb++) {
        float dv = 0.f;
        #pragma unroll
        for (int d = 0; d < 16; d++) dv += q[d] * kvs[jb][h * 16 + d];
        sc[jb] = dv * 0.25f;
        mx = fmaxf(mx, sc[jb]);
    }
    float sum = 0.f;
    #pragma unroll
    for (int jb = 0; jb < 8; jb++) { float e = expf(sc[jb] - mx); sc[jb] = e; sum += e; }
    float o[16] = {};
    #pragma unroll
    for (int jb = 0; jb < 8; jb++) {
        float w = sc[jb];
        #pragma unroll
        for (int d = 0; d < 16; d++) o[d] += w * kvs[jb][128 + h * 16 + d];
    }
    float inv = 1.f / sum;
    size_t ob = ((size_t)qb * SS + s) * 128 + h * 16;
    #pragma unroll
    for (int d = 0; d < 16; d += 2)
        store_hl(Ch, Cl, ob + d, o[d] * inv, o[d + 1] * inv);
}

extern "C" void kernel_launch(void* const* d_in, const int* in_sizes, int n_in,
                              void* d_out, int out_size)
{
    const float* x        = (const float*)d_in[0];
    const float* sp       = (const float*)d_in[1];
    const float* tp       = (const float*)d_in[2];
    const float* lw_in_b  = (const float*)d_in[4];
    const float* lw_out_b = (const float*)d_in[6];
    const float* spat_b   = (const float*)d_in[8];
    const float* temp_b   = (const float*)d_in[10];
    const float* int_in_b = (const float*)d_in[12];
    const float* int_out_b= (const float*)d_in[14];
    const float* ffn_b1   = (const float*)d_in[16];
    const float* ffn_b2   = (const float*)d_in[18];
    const float* ln1_g    = (const float*)d_in[19];
    const float* ln1_b    = (const float*)d_in[20];
    const float* ln2_g    = (const float*)d_in[21];
    const float* ln2_b    = (const float*)d_in[22];
    float* out = (float*)d_out;

    float* f32 = nullptr;
    __nv_bfloat16* bf = nullptr;
    cudaGetSymbolAddress((void**)&f32, g_f32);
    cudaGetSymbolAddress((void**)&bf, g_bf);

    static cudaStream_t s2 = nullptr;
    static cudaEvent_t evF = nullptr, evJ = nullptr;
    static bool init_done = false;
    if (!init_done) {
        cudaFuncSetAttribute(gemm_mma, cudaFuncAttributeMaxDynamicSharedMemorySize, 2 * GST);
        cudaFuncSetAttribute(mcov_mma, cudaFuncAttributeMaxDynamicSharedMemorySize, 2 * CST);
        cudaStreamCreateWithFlags(&s2, cudaStreamNonBlocking);
        cudaEventCreateWithFlags(&evF, cudaEventDisableTiming);
        cudaEventCreateWithFlags(&evJ, cudaEventDisableTiming);
        init_done = true;
    }

    float* qkv   = f32 + F_QKV;
    float* qkv2  = f32 + F_QKV2;
    float* bufb  = f32 + F_BUFB;
    float* bufc  = f32 + F_BUFC;
    float* snf   = f32 + F_SNF;
    float* bM    = f32 + F_M;
    float* bsim  = f32 + F_SIM;

    #define BH(o) (bf + (o))
    #define BL(o, n) (bf + (o) + (n))
    const unsigned NT = 2097152;

    // ---- fork point ----
    cudaEventRecord(evF, 0);
    cudaStreamWaitEvent(s2, evF, 0);

    // ===== main stream: x-chain =====
    {
        CvtSrc cs;
        cs.cnt = 5;
        cs.p[0] = x;                         cs.n[0] = 2097152; cs.off[0] = H_X;
        cs.p[1] = (const float*)d_in[3];     cs.n[1] = 49152;   cs.off[1] = H_LWIN;
        cs.p[2] = (const float*)d_in[5];     cs.n[2] = 16384;   cs.off[2] = H_LWOUT;
        cs.p[3] = (const float*)d_in[15];    cs.n[3] = 65536;   cs.off[3] = H_FW1;
        cs.p[4] = (const float*)d_in[17];    cs.n[4] = 65536;   cs.off[4] = H_FW2;
        cvt_k<<<296, 256>>>(cs);
    }
    gemm_mma<<<dim3(3, 256), 256, 2 * GST>>>(
        BH(H_X), BL(H_X, NT), nullptr, nullptr, BH(H_LWIN), BL(H_LWIN, 49152),
        lw_in_b, qkv, nullptr, nullptr, nullptr, nullptr, nullptr, nullptr,
        nullptr, nullptr, 128, 384, EP_F32, 0);
    lw_attn_k<<<dim3(256, 8), 64>>>(qkv, BH(H_ATT), BL(H_ATT, NT));
    gemm_mma<<<dim3(1, 256), 256, 2 * GST>>>(
        BH(H_ATT), BL(H_ATT, NT), nullptr, nullptr, BH(H_LWOUT), BL(H_LWOUT, 16384),
        lw_out_b, bufb, BH(H_BUFB), BL(H_BUFB, NT), nullptr, nullptr,
        x, nullptr, ln1_g, ln1_b, 128, 128, EP_LN, 0);
    gemm_mma<<<dim3(4, 256), 256, 2 * GST>>>(
        BH(H_BUFB), BL(H_BUFB, NT), nullptr, nullptr, BH(H_FW1), BL(H_FW1, 65536),
        ffn_b1, nullptr, BH(H_BUFH), BL(H_BUFH, 8388608), nullptr, nullptr,
        nullptr, nullptr, nullptr, nullptr, 128, 512, EP_GELU, 0);
    gemm_mma<<<dim3(1, 256), 256, 2 * GST>>>(
        BH(H_BUFH), BL(H_BUFH, 8388608), nullptr, nullptr, BH(H_FW2), BL(H_FW2, 65536),
        ffn_b2, bufc, nullptr, nullptr, nullptr, nullptr,
        bufb, nullptr, ln2_g, ln2_b, 512, 128, EP_LN2, 0);

    // ===== stream 2: spatio-temporal chain =====
    {
        CvtSrc cs;
        cs.cnt = 6;
        cs.p[0] = sp;                        cs.n[0] = 2097152; cs.off[0] = H_SP;
        cs.p[1] = tp;                        cs.n[1] = 2097152; cs.off[1] = H_TP;
        cs.p[2] = (const float*)d_in[7];     cs.n[2] = 16384;   cs.off[2] = H_SPATW;
        cs.p[3] = (const float*)d_in[9];     cs.n[3] = 16384;   cs.off[3] = H_TEMPW;
        cs.p[4] = (const float*)d_in[11];    cs.n[4] = 49152;   cs.off[4] = H_INTIN;
        cs.p[5] = (const float*)d_in[13];    cs.n[5] = 16384;   cs.off[5] = H_INTOUT;
        cvt_k<<<296, 256, 0, s2>>>(cs);
    }
    zero_k<<<512, 256, 0, s2>>>(bM, 8 * 128 * 128);
    gemm_mma<<<dim3(1, 256), 256, 2 * GST, s2>>>(
        BH(H_SP), BL(H_SP, NT), nullptr, nullptr, BH(H_SPATW), BL(H_SPATW, 16384),
        spat_b, snf, BH(H_SE), BL(H_SE, NT), BH(H_SN), BL(H_SN, NT),
        nullptr, nullptr, nullptr, nullptr, 128, 128, EP_COS, 0);
    gemm_mma<<<dim3(1, 256), 256, 2 * GST, s2>>>(
        BH(H_TP), BL(H_TP, NT), nullptr, nullptr, BH(H_TEMPW), BL(H_TEMPW, 16384),
        temp_b, nullptr, BH(H_TE), BL(H_TE, NT), BH(H_TN), BL(H_TN, NT),
        nullptr, nullptr, nullptr, nullptr, 128, 128, EP_COS, 0);
    mcov_mma<<<dim3(16, 8), 256, 2 * CST, s2>>>(
        BH(H_SN), BL(H_SN, NT), BH(H_TN), BL(H_TN, NT), bM);
    cvtm_k<<<128, 256, 0, s2>>>(bM, BH(H_M), BL(H_M, 131072), 131072);
    gemm_mma<<<dim3(1, 256), 256, 2 * GST, s2>>>(
        BH(H_TN), BL(H_TN, NT), nullptr, nullptr, BH(H_M), BL(H_M, 131072),
        nullptr, bsim, nullptr, nullptr, nullptr, nullptr,
        snf, nullptr, nullptr, nullptr, 128, 0, EP_SIMDOT, 16384);
    gemm_mma<<<dim3(3, 256), 256, 2 * GST, s2>>>(
        BH(H_SE), BL(H_SE, NT), BH(H_TE), BL(H_TE, NT), BH(H_INTIN), BL(H_INTIN, 49152),
        int_in_b, qkv2, nullptr, nullptr, nullptr, nullptr, nullptr, nullptr,
        nullptr, nullptr, 128, 384, EP_F32, 0);
    int_attn_k<<<SS, 64, 0, s2>>>(qkv2, BH(H_ATT2), BL(H_ATT2, NT));
    cudaEventRecord(evJ, s2);

    // ---- join + final ----
    cudaStreamWaitEvent(0, evJ, 0);
    gemm_mma<<<dim3(1, 256), 256, 2 * GST>>>(
        BH(H_ATT2), BL(H_ATT2, NT), nullptr, nullptr, BH(H_INTOUT), BL(H_INTOUT, 16384),
        int_out_b, out, nullptr, nullptr, nullptr, nullptr,
        bufc, bsim, nullptr, nullptr, 128, 128, EP_FINAL, 0);
}